// round 1
// baseline (speedup 1.0000x reference)
#include <cuda_runtime.h>

#define SS 2048
#define DD 64
#define NH 16
#define NB 2
#define TQ 128
#define TK 128
#define TK2 64
#define LDQ 132   // padded row stride (floats) for 128-col tiles
#define LDV 68    // padded row stride for 64-col V tile
#define NEGV -1000000000.0f

// smem (floats): pass1 { Qs[64][LDQ], Ks[64][LDQ] } / pass2 { Ps[64][LDQ], Vs[64][LDV] } union,
// then m[TQ], linv[TQ]
#define SM_FLOATS (2*64*LDQ + 2*TQ)

__global__ __launch_bounds__(256, 2)
void sdpa_kernel(const float* __restrict__ qg, const float* __restrict__ kg,
                 const float* __restrict__ vg, const int* __restrict__ maskg,
                 float* __restrict__ outg, float* __restrict__ probg,
                 float* __restrict__ attng)
{
    extern __shared__ float sm[];
    float* Qs = sm;                    // pass1: [d][q] 64 x LDQ
    float* Ks = sm + 64*LDQ;           // pass1: [d][k] 64 x LDQ
    float* Ps = sm;                    // pass2: [k][q] 64 x LDQ
    float* Vs = sm + 64*LDQ;           // pass2: [k][d] 64 x LDV
    float* sm_m  = sm + 2*64*LDQ;      // [TQ]
    float* sm_li = sm + 2*64*LDQ + TQ; // [TQ]

    const int tid = threadIdx.x;
    const int tx  = tid & 15;
    const int ty  = tid >> 4;

    const int q0 = blockIdx.x * TQ;
    const int h  = blockIdx.y;
    const int b  = blockIdx.z;
    const int bh = b*NH + h;

    const float* qbase = qg + ((size_t)bh*SS + q0) * DD;
    const float* kbase = kg + (size_t)bh*SS*DD;
    const float* vbase = vg + (size_t)bh*SS*DD;
    const int*   mbase = maskg + ((size_t)b*SS + q0) * SS;
    float* attnbase = attng + ((size_t)bh*SS + q0) * SS;
    float* probbase = probg + ((size_t)bh*SS + q0) * SS;
    float* outbase  = outg  + ((size_t)bh*SS + q0) * DD;

    // ---- load Q tile transposed: Qs[d][qrow] ----
    for (int i = tid; i < TQ*(DD/4); i += 256) {
        int qrow = i >> 4;
        int d4   = (i & 15) << 2;
        float4 val = *reinterpret_cast<const float4*>(qbase + (size_t)qrow*DD + d4);
        Qs[(d4+0)*LDQ + qrow] = val.x;
        Qs[(d4+1)*LDQ + qrow] = val.y;
        Qs[(d4+2)*LDQ + qrow] = val.z;
        Qs[(d4+3)*LDQ + qrow] = val.w;
    }

    float mrun[8], lrun[8];
    #pragma unroll
    for (int i = 0; i < 8; i++) { mrun[i] = -1e30f; lrun[i] = 0.0f; }

    // ================= PASS 1: scores, attn, online (m,l) =================
    for (int kt = 0; kt < SS/TK; kt++) {
        __syncthreads();   // protect Ks (prev compute) and Qs (first iter)
        for (int i = tid; i < TK*(DD/4); i += 256) {
            int krow = i >> 4;
            int d4   = (i & 15) << 2;
            float4 val = *reinterpret_cast<const float4*>(
                kbase + (size_t)(kt*TK + krow)*DD + d4);
            Ks[(d4+0)*LDQ + krow] = val.x;
            Ks[(d4+1)*LDQ + krow] = val.y;
            Ks[(d4+2)*LDQ + krow] = val.z;
            Ks[(d4+3)*LDQ + krow] = val.w;
        }
        __syncthreads();

        float acc[8][8];
        #pragma unroll
        for (int a = 0; a < 8; a++)
            #pragma unroll
            for (int c = 0; c < 8; c++) acc[a][c] = 0.0f;

        #pragma unroll 4
        for (int d = 0; d < DD; d++) {
            float4 qa = *reinterpret_cast<const float4*>(&Qs[d*LDQ + ty*8]);
            float4 qb = *reinterpret_cast<const float4*>(&Qs[d*LDQ + ty*8 + 4]);
            float4 ka = *reinterpret_cast<const float4*>(&Ks[d*LDQ + tx*8]);
            float4 kb = *reinterpret_cast<const float4*>(&Ks[d*LDQ + tx*8 + 4]);
            float qv[8] = {qa.x,qa.y,qa.z,qa.w,qb.x,qb.y,qb.z,qb.w};
            float kv[8] = {ka.x,ka.y,ka.z,ka.w,kb.x,kb.y,kb.z,kb.w};
            #pragma unroll
            for (int a = 0; a < 8; a++)
                #pragma unroll
                for (int c = 0; c < 8; c++)
                    acc[a][c] = fmaf(qv[a], kv[c], acc[a][c]);
        }

        const int kcol0 = kt*TK + tx*8;
        #pragma unroll
        for (int a = 0; a < 8; a++) {
            const int qrow = ty*8 + a;
            const int* mrow = mbase + (size_t)qrow*SS + kcol0;
            int4 m0 = *reinterpret_cast<const int4*>(mrow);
            int4 m1 = *reinterpret_cast<const int4*>(mrow + 4);
            float s[8];
            s[0] = fmaf(acc[a][0], 0.125f, m0.x ? 0.0f : NEGV);
            s[1] = fmaf(acc[a][1], 0.125f, m0.y ? 0.0f : NEGV);
            s[2] = fmaf(acc[a][2], 0.125f, m0.z ? 0.0f : NEGV);
            s[3] = fmaf(acc[a][3], 0.125f, m0.w ? 0.0f : NEGV);
            s[4] = fmaf(acc[a][4], 0.125f, m1.x ? 0.0f : NEGV);
            s[5] = fmaf(acc[a][5], 0.125f, m1.y ? 0.0f : NEGV);
            s[6] = fmaf(acc[a][6], 0.125f, m1.z ? 0.0f : NEGV);
            s[7] = fmaf(acc[a][7], 0.125f, m1.w ? 0.0f : NEGV);

            float* arow = attnbase + (size_t)qrow*SS + kcol0;
            *reinterpret_cast<float4*>(arow)     = make_float4(s[0],s[1],s[2],s[3]);
            *reinterpret_cast<float4*>(arow + 4) = make_float4(s[4],s[5],s[6],s[7]);

            float tmax = fmaxf(fmaxf(fmaxf(s[0],s[1]), fmaxf(s[2],s[3])),
                               fmaxf(fmaxf(s[4],s[5]), fmaxf(s[6],s[7])));
            float mo = mrun[a];
            if (tmax > mo) {
                lrun[a] *= __expf(mo - tmax);
                mo = tmax;
                mrun[a] = tmax;
            }
            float ls = __expf(s[0]-mo) + __expf(s[1]-mo) + __expf(s[2]-mo) + __expf(s[3]-mo)
                     + __expf(s[4]-mo) + __expf(s[5]-mo) + __expf(s[6]-mo) + __expf(s[7]-mo);
            lrun[a] += ls;
        }
    }

    // reduce (m,l) across the 16 tx lanes (same warp, xor butterfly)
    #pragma unroll
    for (int a = 0; a < 8; a++) {
        float m = mrun[a], l = lrun[a];
        #pragma unroll
        for (int off = 1; off < 16; off <<= 1) {
            float m2 = __shfl_xor_sync(0xffffffffu, m, off);
            float l2 = __shfl_xor_sync(0xffffffffu, l, off);
            float mn = fmaxf(m, m2);
            l = l*__expf(m - mn) + l2*__expf(m2 - mn);
            m = mn;
        }
        if (tx == 0) {
            sm_m[ty*8 + a]  = m;
            sm_li[ty*8 + a] = 1.0f / l;
        }
    }
    __syncthreads();

    // ================= PASS 2: prob + output =================
    const int dx   = tx & 7;
    const int kpar = tx >> 3;
    float oacc[8][8];
    #pragma unroll
    for (int a = 0; a < 8; a++)
        #pragma unroll
        for (int c = 0; c < 8; c++) oacc[a][c] = 0.0f;

    for (int kt = 0; kt < SS/TK2; kt++) {
        __syncthreads();   // protect Ps/Vs from previous compute
        const int kb0 = kt*TK2;

        // convert attn -> prob, stage Ps[k][q]
        for (int i = tid; i < TQ*(TK2/4); i += 256) {
            int qrow = i >> 4;
            int k4   = (i & 15) << 2;
            size_t gi = (size_t)qrow*SS + kb0 + k4;
            float4 sv = *reinterpret_cast<const float4*>(attnbase + gi);
            float mm = sm_m[qrow];
            float li = sm_li[qrow];
            float4 pv;
            pv.x = __expf(sv.x - mm) * li;
            pv.y = __expf(sv.y - mm) * li;
            pv.z = __expf(sv.z - mm) * li;
            pv.w = __expf(sv.w - mm) * li;
            *reinterpret_cast<float4*>(probbase + gi) = pv;
            Ps[(k4+0)*LDQ + qrow] = pv.x;
            Ps[(k4+1)*LDQ + qrow] = pv.y;
            Ps[(k4+2)*LDQ + qrow] = pv.z;
            Ps[(k4+3)*LDQ + qrow] = pv.w;
        }
        // load V tile: Vs[k][d]
        for (int i = tid; i < TK2*(DD/4); i += 256) {
            int krow = i >> 4;
            int d4   = (i & 15) << 2;
            float4 val = *reinterpret_cast<const float4*>(
                vbase + (size_t)(kb0 + krow)*DD + d4);
            *reinterpret_cast<float4*>(&Vs[krow*LDV + d4]) = val;
        }
        __syncthreads();

        #pragma unroll 2
        for (int kk = 0; kk < TK2/2; kk++) {
            int kl = kk*2 + kpar;
            float4 pa = *reinterpret_cast<const float4*>(&Ps[kl*LDQ + ty*8]);
            float4 pb = *reinterpret_cast<const float4*>(&Ps[kl*LDQ + ty*8 + 4]);
            float4 va = *reinterpret_cast<const float4*>(&Vs[kl*LDV + dx*8]);
            float4 vb = *reinterpret_cast<const float4*>(&Vs[kl*LDV + dx*8 + 4]);
            float pv[8] = {pa.x,pa.y,pa.z,pa.w,pb.x,pb.y,pb.z,pb.w};
            float vv[8] = {va.x,va.y,va.z,va.w,vb.x,vb.y,vb.z,vb.w};
            #pragma unroll
            for (int a = 0; a < 8; a++)
                #pragma unroll
                for (int c = 0; c < 8; c++)
                    oacc[a][c] = fmaf(pv[a], vv[c], oacc[a][c]);
        }
    }

    // combine k-parity halves (lane xor 8 has same q-rows / d-cols, other parity)
    #pragma unroll
    for (int a = 0; a < 8; a++)
        #pragma unroll
        for (int c = 0; c < 8; c++)
            oacc[a][c] += __shfl_xor_sync(0xffffffffu, oacc[a][c], 8);

    if (kpar == 0) {
        #pragma unroll
        for (int a = 0; a < 8; a++) {
            float* orow = outbase + (size_t)(ty*8 + a)*DD + dx*8;
            *reinterpret_cast<float4*>(orow) =
                make_float4(oacc[a][0], oacc[a][1], oacc[a][2], oacc[a][3]);
            *reinterpret_cast<float4*>(orow + 4) =
                make_float4(oacc[a][4], oacc[a][5], oacc[a][6], oacc[a][7]);
        }
    }
}

extern "C" void kernel_launch(void* const* d_in, const int* in_sizes, int n_in,
                              void* d_out, int out_size) {
    const float* q    = (const float*)d_in[0];
    const float* k    = (const float*)d_in[1];
    const float* v    = (const float*)d_in[2];
    const int*   mask = (const int*)d_in[3];

    float* out = (float*)d_out;
    const size_t n_out  = (size_t)NB*NH*SS*DD;   // 4,194,304
    const size_t n_attn = (size_t)NB*NH*SS*SS;   // 134,217,728
    float* prob = out + n_out;                   // attn_prob second
    float* attn = prob + n_attn;                 // attn (raw scores) third

    const int smem_bytes = SM_FLOATS * (int)sizeof(float);   // 68,608 B
    cudaFuncSetAttribute(sdpa_kernel,
                         cudaFuncAttributeMaxDynamicSharedMemorySize, smem_bytes);

    dim3 grid(SS/TQ, NH, NB);   // (16, 16, 2)
    sdpa_kernel<<<grid, 256, smem_bytes>>>(q, k, v, mask, out, prob, attn);
}

// round 2
// speedup vs baseline: 1.0907x; 1.0907x over previous
#include <cuda_runtime.h>

#define SS 2048
#define DD 64
#define NH 16
#define NB 2
#define TQ 128
#define TK 128
#define TK2 64
#define LDQ 132   // padded row stride (floats); 132*4=528B, 16B-aligned rows
#define LDV 68    // padded row stride for 64-col V tile; 68*4=272B, 16B-aligned
#define NEGV -1000000000.0f

typedef unsigned long long ull;

#define SM_FLOATS (2*64*LDQ + 2*TQ)

__device__ __forceinline__ ull pack2(float x) {
    ull r;
    asm("mov.b64 %0, {%1, %1};" : "=l"(r) : "f"(x));
    return r;
}
__device__ __forceinline__ ull fma2(ull a, ull b, ull c) {
    ull d;
    asm("fma.rn.f32x2 %0, %1, %2, %3;" : "=l"(d) : "l"(a), "l"(b), "l"(c));
    return d;
}
__device__ __forceinline__ ull add2(ull a, ull b) {
    ull d;
    asm("add.rn.f32x2 %0, %1, %2;" : "=l"(d) : "l"(a), "l"(b));
    return d;
}
__device__ __forceinline__ float2 unpack2(ull v) {
    float2 f;
    asm("mov.b64 {%0, %1}, %2;" : "=f"(f.x), "=f"(f.y) : "l"(v));
    return f;
}

__global__ __launch_bounds__(256, 2)
void sdpa_kernel(const float* __restrict__ qg, const float* __restrict__ kg,
                 const float* __restrict__ vg, const int* __restrict__ maskg,
                 float* __restrict__ outg, float* __restrict__ probg,
                 float* __restrict__ attng)
{
    extern __shared__ float sm[];
    float* Qs = sm;                    // pass1: [d][q] 64 x LDQ
    float* Ks = sm + 64*LDQ;           // pass1: [d][k] 64 x LDQ
    float* Ps = sm;                    // pass2: [k][q] 64 x LDQ
    float* Vs = sm + 64*LDQ;           // pass2: [k][d] 64 x LDV
    float* sm_m  = sm + 2*64*LDQ;      // [TQ]
    float* sm_li = sm + 2*64*LDQ + TQ; // [TQ]

    const int tid = threadIdx.x;
    const int tx  = tid & 15;
    const int ty  = tid >> 4;

    const int q0 = blockIdx.x * TQ;
    const int h  = blockIdx.y;
    const int b  = blockIdx.z;
    const int bh = b*NH + h;

    const float* qbase = qg + ((size_t)bh*SS + q0) * DD;
    const float* kbase = kg + (size_t)bh*SS*DD;
    const float* vbase = vg + (size_t)bh*SS*DD;
    const int*   mbase = maskg + ((size_t)b*SS + q0) * SS;
    float* attnbase = attng + ((size_t)bh*SS + q0) * SS;
    float* probbase = probg + ((size_t)bh*SS + q0) * SS;
    float* outbase  = outg  + ((size_t)bh*SS + q0) * DD;

    // ---- load Q tile transposed: Qs[d][qrow] ----
    for (int i = tid; i < TQ*(DD/4); i += 256) {
        int qrow = i >> 4;
        int d4   = (i & 15) << 2;
        float4 val = *reinterpret_cast<const float4*>(qbase + (size_t)qrow*DD + d4);
        Qs[(d4+0)*LDQ + qrow] = val.x;
        Qs[(d4+1)*LDQ + qrow] = val.y;
        Qs[(d4+2)*LDQ + qrow] = val.z;
        Qs[(d4+3)*LDQ + qrow] = val.w;
    }

    float mrun[8], lrun[8];
    #pragma unroll
    for (int i = 0; i < 8; i++) { mrun[i] = -1e30f; lrun[i] = 0.0f; }

    // ================= PASS 1: scores, attn, online (m,l) =================
    for (int kt = 0; kt < SS/TK; kt++) {
        __syncthreads();
        for (int i = tid; i < TK*(DD/4); i += 256) {
            int krow = i >> 4;
            int d4   = (i & 15) << 2;
            float4 val = *reinterpret_cast<const float4*>(
                kbase + (size_t)(kt*TK + krow)*DD + d4);
            Ks[(d4+0)*LDQ + krow] = val.x;
            Ks[(d4+1)*LDQ + krow] = val.y;
            Ks[(d4+2)*LDQ + krow] = val.z;
            Ks[(d4+3)*LDQ + krow] = val.w;
        }
        __syncthreads();

        ull acc2[8][4];   // 8 q-rows x 4 packed k-pairs
        #pragma unroll
        for (int a = 0; a < 8; a++)
            #pragma unroll
            for (int c = 0; c < 4; c++) acc2[a][c] = 0ull;

        #pragma unroll 4
        for (int d = 0; d < DD; d++) {
            float4 qa = *reinterpret_cast<const float4*>(&Qs[d*LDQ + ty*8]);
            float4 qb = *reinterpret_cast<const float4*>(&Qs[d*LDQ + ty*8 + 4]);
            ulonglong2 k01 = *reinterpret_cast<const ulonglong2*>(&Ks[d*LDQ + tx*8]);
            ulonglong2 k23 = *reinterpret_cast<const ulonglong2*>(&Ks[d*LDQ + tx*8 + 4]);
            float qv[8] = {qa.x,qa.y,qa.z,qa.w,qb.x,qb.y,qb.z,qb.w};
            ull   kp[4] = {k01.x, k01.y, k23.x, k23.y};
            #pragma unroll
            for (int a = 0; a < 8; a++) {
                ull qq = pack2(qv[a]);
                #pragma unroll
                for (int c = 0; c < 4; c++)
                    acc2[a][c] = fma2(qq, kp[c], acc2[a][c]);
            }
        }

        const int kcol0 = kt*TK + tx*8;
        #pragma unroll
        for (int a = 0; a < 8; a++) {
            const int qrow = ty*8 + a;
            const int* mrow = mbase + (size_t)qrow*SS + kcol0;
            int4 m0 = *reinterpret_cast<const int4*>(mrow);
            int4 m1 = *reinterpret_cast<const int4*>(mrow + 4);
            float2 p0 = unpack2(acc2[a][0]);
            float2 p1 = unpack2(acc2[a][1]);
            float2 p2 = unpack2(acc2[a][2]);
            float2 p3 = unpack2(acc2[a][3]);
            float s[8];
            s[0] = fmaf(p0.x, 0.125f, m0.x ? 0.0f : NEGV);
            s[1] = fmaf(p0.y, 0.125f, m0.y ? 0.0f : NEGV);
            s[2] = fmaf(p1.x, 0.125f, m0.z ? 0.0f : NEGV);
            s[3] = fmaf(p1.y, 0.125f, m0.w ? 0.0f : NEGV);
            s[4] = fmaf(p2.x, 0.125f, m1.x ? 0.0f : NEGV);
            s[5] = fmaf(p2.y, 0.125f, m1.y ? 0.0f : NEGV);
            s[6] = fmaf(p3.x, 0.125f, m1.z ? 0.0f : NEGV);
            s[7] = fmaf(p3.y, 0.125f, m1.w ? 0.0f : NEGV);

            float* arow = attnbase + (size_t)qrow*SS + kcol0;
            *reinterpret_cast<float4*>(arow)     = make_float4(s[0],s[1],s[2],s[3]);
            *reinterpret_cast<float4*>(arow + 4) = make_float4(s[4],s[5],s[6],s[7]);

            float tmax = fmaxf(fmaxf(fmaxf(s[0],s[1]), fmaxf(s[2],s[3])),
                               fmaxf(fmaxf(s[4],s[5]), fmaxf(s[6],s[7])));
            float mo = mrun[a];
            if (tmax > mo) {
                lrun[a] *= __expf(mo - tmax);
                mo = tmax;
                mrun[a] = tmax;
            }
            float ls = __expf(s[0]-mo) + __expf(s[1]-mo) + __expf(s[2]-mo) + __expf(s[3]-mo)
                     + __expf(s[4]-mo) + __expf(s[5]-mo) + __expf(s[6]-mo) + __expf(s[7]-mo);
            lrun[a] += ls;
        }
    }

    // reduce (m,l) across the 16 tx lanes
    #pragma unroll
    for (int a = 0; a < 8; a++) {
        float m = mrun[a], l = lrun[a];
        #pragma unroll
        for (int off = 1; off < 16; off <<= 1) {
            float m2 = __shfl_xor_sync(0xffffffffu, m, off);
            float l2 = __shfl_xor_sync(0xffffffffu, l, off);
            float mn = fmaxf(m, m2);
            l = l*__expf(m - mn) + l2*__expf(m2 - mn);
            m = mn;
        }
        if (tx == 0) {
            sm_m[ty*8 + a]  = m;
            sm_li[ty*8 + a] = 1.0f / l;
        }
    }
    __syncthreads();

    // ================= PASS 2: prob + output =================
    const int dx   = tx & 7;
    const int kpar = tx >> 3;
    ull oacc2[8][4];   // 8 q-rows x 4 packed d-pairs
    #pragma unroll
    for (int a = 0; a < 8; a++)
        #pragma unroll
        for (int c = 0; c < 4; c++) oacc2[a][c] = 0ull;

    for (int kt = 0; kt < SS/TK2; kt++) {
        __syncthreads();
        const int kb0 = kt*TK2;

        // convert attn -> prob, stage Ps[k][q]
        for (int i = tid; i < TQ*(TK2/4); i += 256) {
            int qrow = i >> 4;
            int k4   = (i & 15) << 2;
            size_t gi = (size_t)qrow*SS + kb0 + k4;
            float4 sv = *reinterpret_cast<const float4*>(attnbase + gi);
            float mm = sm_m[qrow];
            float li = sm_li[qrow];
            float4 pv;
            pv.x = __expf(sv.x - mm) * li;
            pv.y = __expf(sv.y - mm) * li;
            pv.z = __expf(sv.z - mm) * li;
            pv.w = __expf(sv.w - mm) * li;
            *reinterpret_cast<float4*>(probbase + gi) = pv;
            Ps[(k4+0)*LDQ + qrow] = pv.x;
            Ps[(k4+1)*LDQ + qrow] = pv.y;
            Ps[(k4+2)*LDQ + qrow] = pv.z;
            Ps[(k4+3)*LDQ + qrow] = pv.w;
        }
        // load V tile: Vs[k][d]
        for (int i = tid; i < TK2*(DD/4); i += 256) {
            int krow = i >> 4;
            int d4   = (i & 15) << 2;
            float4 val = *reinterpret_cast<const float4*>(
                vbase + (size_t)(kb0 + krow)*DD + d4);
            *reinterpret_cast<float4*>(&Vs[krow*LDV + d4]) = val;
        }
        __syncthreads();

        #pragma unroll 2
        for (int kk = 0; kk < TK2/2; kk++) {
            int kl = kk*2 + kpar;
            float4 pa = *reinterpret_cast<const float4*>(&Ps[kl*LDQ + ty*8]);
            float4 pb = *reinterpret_cast<const float4*>(&Ps[kl*LDQ + ty*8 + 4]);
            ulonglong2 v01 = *reinterpret_cast<const ulonglong2*>(&Vs[kl*LDV + dx*8]);
            ulonglong2 v23 = *reinterpret_cast<const ulonglong2*>(&Vs[kl*LDV + dx*8 + 4]);
            float pv[8] = {pa.x,pa.y,pa.z,pa.w,pb.x,pb.y,pb.z,pb.w};
            ull   vp[4] = {v01.x, v01.y, v23.x, v23.y};
            #pragma unroll
            for (int a = 0; a < 8; a++) {
                ull pp = pack2(pv[a]);
                #pragma unroll
                for (int c = 0; c < 4; c++)
                    oacc2[a][c] = fma2(pp, vp[c], oacc2[a][c]);
            }
        }
    }

    // combine k-parity halves (lane xor 8)
    #pragma unroll
    for (int a = 0; a < 8; a++)
        #pragma unroll
        for (int c = 0; c < 4; c++) {
            ull other = __shfl_xor_sync(0xffffffffu, oacc2[a][c], 8);
            oacc2[a][c] = add2(oacc2[a][c], other);
        }

    if (kpar == 0) {
        #pragma unroll
        for (int a = 0; a < 8; a++) {
            float* orow = outbase + (size_t)(ty*8 + a)*DD + dx*8;
            ulonglong2 w0; w0.x = oacc2[a][0]; w0.y = oacc2[a][1];
            ulonglong2 w1; w1.x = oacc2[a][2]; w1.y = oacc2[a][3];
            *reinterpret_cast<ulonglong2*>(orow)     = w0;
            *reinterpret_cast<ulonglong2*>(orow + 4) = w1;
        }
    }
}

extern "C" void kernel_launch(void* const* d_in, const int* in_sizes, int n_in,
                              void* d_out, int out_size) {
    const float* q    = (const float*)d_in[0];
    const float* k    = (const float*)d_in[1];
    const float* v    = (const float*)d_in[2];
    const int*   mask = (const int*)d_in[3];

    float* out = (float*)d_out;
    const size_t n_out  = (size_t)NB*NH*SS*DD;
    const size_t n_attn = (size_t)NB*NH*SS*SS;
    float* prob = out + n_out;
    float* attn = prob + n_attn;

    const int smem_bytes = SM_FLOATS * (int)sizeof(float);
    cudaFuncSetAttribute(sdpa_kernel,
                         cudaFuncAttributeMaxDynamicSharedMemorySize, smem_bytes);

    dim3 grid(SS/TQ, NH, NB);
    sdpa_kernel<<<grid, 256, smem_bytes>>>(q, k, v, mask, out, prob, attn);
}

// round 4
// speedup vs baseline: 1.0994x; 1.0080x over previous
#include <cuda_runtime.h>
#include <cstdint>

#define SS 2048
#define DD 64
#define NH 16
#define NB 2
#define NEGV -1000000000.0f

#define LDQ 68   // row stride (floats) for Qs/Ks/Ps: conflict-free frag reads
#define LDV 65   // row stride for Vt

// smem floats: Qs[128*LDQ] | Ks[128*LDQ] (pass2: Ps overlays Qs, Vt overlays Ks) | m[128] | li[128]
#define SM_QS 0
#define SM_KS (128*LDQ)
#define SM_M  (2*128*LDQ)
#define SM_LI (2*128*LDQ + 128)
#define SM_FLOATS (2*128*LDQ + 256)

#define MMA_TF32(d, a0,a1,a2,a3, b0,b1) \
    asm volatile("mma.sync.aligned.m16n8k8.row.col.f32.tf32.tf32.f32 " \
        "{%0,%1,%2,%3}, {%4,%5,%6,%7}, {%8,%9}, {%0,%1,%2,%3};" \
        : "+f"((d)[0]), "+f"((d)[1]), "+f"((d)[2]), "+f"((d)[3]) \
        : "r"(a0), "r"(a1), "r"(a2), "r"(a3), "r"(b0), "r"(b1))

__device__ __forceinline__ void split_tf32(float x, uint32_t& hi, uint32_t& lo) {
    asm("cvt.rna.tf32.f32 %0, %1;" : "=r"(hi) : "f"(x));
    float l = x - __uint_as_float(hi);
    asm("cvt.rna.tf32.f32 %0, %1;" : "=r"(lo) : "f"(l));
}

__global__ __launch_bounds__(256, 2)
void sdpa_mma_kernel(const float* __restrict__ qg, const float* __restrict__ kg,
                     const float* __restrict__ vg, const int* __restrict__ maskg,
                     float* __restrict__ outg, float* __restrict__ probg,
                     float* __restrict__ attng)
{
    extern __shared__ float sm[];
    float* Qs = sm + SM_QS;    // pass1 Q [128][LDQ]; pass2: Ps
    float* Ks = sm + SM_KS;    // pass1 K [128][LDQ]; pass2: Vt [64][LDV]
    float* Ps = Qs;
    float* Vt = Ks;
    float* sm_m  = sm + SM_M;
    float* sm_li = sm + SM_LI;

    const int tid = threadIdx.x;
    const int wid = tid >> 5;
    const int lid = tid & 31;
    const int grp = lid >> 2;   // 0..7
    const int tig = lid & 3;    // 0..3
    const int mrow0 = wid * 16; // warp's S-row base

    const int q0 = blockIdx.x * 128;
    const int h  = blockIdx.y;
    const int b  = blockIdx.z;
    const int bh = b*NH + h;

    const float* qbase = qg + ((size_t)bh*SS + q0) * DD;
    const float* kbase = kg + (size_t)bh*SS*DD;
    const float* vbase = vg + (size_t)bh*SS*DD;
    const int*   mbase = maskg + ((size_t)b*SS + q0) * SS;
    float* attnbase = attng + ((size_t)bh*SS + q0) * SS;
    float* probbase = probg + ((size_t)bh*SS + q0) * SS;
    float* outbase  = outg  + ((size_t)bh*SS + q0) * DD;

    // ---- stage Q [128][64] ----
    for (int i = tid; i < 128*16; i += 256) {
        int row = i >> 4, d4 = (i & 15) << 2;
        float4 v = *reinterpret_cast<const float4*>(qbase + (size_t)row*DD + d4);
        *reinterpret_cast<float4*>(&Qs[row*LDQ + d4]) = v;
    }

    float mrun[2] = {-1e30f, -1e30f};
    float lrun[2] = {0.0f, 0.0f};

    // ================= PASS 1 =================
    for (int kt = 0; kt < 16; kt++) {
        __syncthreads();   // prior compute done; safe to restage K
        for (int i = tid; i < 128*16; i += 256) {
            int row = i >> 4, d4 = (i & 15) << 2;
            float4 v = *reinterpret_cast<const float4*>(
                kbase + (size_t)(kt*128 + row)*DD + d4);
            *reinterpret_cast<float4*>(&Ks[row*LDQ + d4]) = v;
        }
        __syncthreads();

        float acc[16][4];
        #pragma unroll
        for (int n = 0; n < 16; n++) {
            acc[n][0] = 0.f; acc[n][1] = 0.f; acc[n][2] = 0.f; acc[n][3] = 0.f;
        }

        #pragma unroll 2
        for (int kk = 0; kk < 8; kk++) {
            const float* q0p = &Qs[(mrow0 + grp)*LDQ + kk*8 + tig];
            const float* q1p = q0p + 8*LDQ;
            uint32_t ah[4], al[4];
            split_tf32(q0p[0], ah[0], al[0]);
            split_tf32(q1p[0], ah[1], al[1]);
            split_tf32(q0p[4], ah[2], al[2]);
            split_tf32(q1p[4], ah[3], al[3]);
            #pragma unroll
            for (int n = 0; n < 16; n++) {
                const float* kp = &Ks[(n*8 + grp)*LDQ + kk*8 + tig];
                uint32_t bh0, bl0, bh1, bl1;
                split_tf32(kp[0], bh0, bl0);
                split_tf32(kp[4], bh1, bl1);
                MMA_TF32(acc[n], ah[0], ah[1], ah[2], ah[3], bh0, bh1);
                MMA_TF32(acc[n], ah[0], ah[1], ah[2], ah[3], bl0, bl1);
                MMA_TF32(acc[n], al[0], al[1], al[2], al[3], bh0, bh1);
            }
        }

        // ---- epilogue: scale + mask + attn STG + online (m,l) ----
        float tmax[2] = {-1e30f, -1e30f};
        #pragma unroll
        for (int n = 0; n < 16; n++) {
            const int kcol = kt*128 + n*8 + 2*tig;
            #pragma unroll
            for (int hh = 0; hh < 2; hh++) {
                const int row = mrow0 + grp + 8*hh;
                int2 mm = *reinterpret_cast<const int2*>(mbase + (size_t)row*SS + kcol);
                float s0 = fmaf(acc[n][2*hh+0], 0.125f, mm.x ? 0.0f : NEGV);
                float s1 = fmaf(acc[n][2*hh+1], 0.125f, mm.y ? 0.0f : NEGV);
                *reinterpret_cast<float2*>(attnbase + (size_t)row*SS + kcol) =
                    make_float2(s0, s1);
                acc[n][2*hh+0] = s0; acc[n][2*hh+1] = s1;
                tmax[hh] = fmaxf(tmax[hh], fmaxf(s0, s1));
            }
        }
        #pragma unroll
        for (int hh = 0; hh < 2; hh++) {
            float tm = tmax[hh];
            tm = fmaxf(tm, __shfl_xor_sync(0xffffffffu, tm, 1));
            tm = fmaxf(tm, __shfl_xor_sync(0xffffffffu, tm, 2));
            float newm = fmaxf(mrun[hh], tm);
            lrun[hh] *= __expf(mrun[hh] - newm);
            float ls = 0.0f;
            #pragma unroll
            for (int n = 0; n < 16; n++) {
                ls += __expf(acc[n][2*hh+0] - newm);
                ls += __expf(acc[n][2*hh+1] - newm);
            }
            ls += __shfl_xor_sync(0xffffffffu, ls, 1);
            ls += __shfl_xor_sync(0xffffffffu, ls, 2);
            lrun[hh] += ls;
            mrun[hh] = newm;
        }
    }

    // ---- publish (m, 1/l) per row ----
    if (tig == 0) {
        #pragma unroll
        for (int hh = 0; hh < 2; hh++) {
            sm_m [mrow0 + grp + 8*hh] = mrun[hh];
            sm_li[mrow0 + grp + 8*hh] = 1.0f / lrun[hh];
        }
    }
    __syncthreads();

    // ================= PASS 2 =================
    float oacc[8][4];
    #pragma unroll
    for (int n = 0; n < 8; n++) {
        oacc[n][0] = 0.f; oacc[n][1] = 0.f; oacc[n][2] = 0.f; oacc[n][3] = 0.f;
    }

    for (int kt = 0; kt < 32; kt++) {
        const int kb = kt*64;
        __syncthreads();   // prior MMA reads done; safe to restage Ps/Vt
        // stage P = prob (re-read attn, exp, normalize) + write prob
        for (int i = tid; i < 128*16; i += 256) {
            int row = i >> 4, k4 = (i & 15) << 2;
            size_t gi = (size_t)row*SS + kb + k4;
            float4 sv = *reinterpret_cast<const float4*>(attnbase + gi);
            float mm = sm_m[row], li = sm_li[row];
            float4 pv;
            pv.x = __expf(sv.x - mm) * li;
            pv.y = __expf(sv.y - mm) * li;
            pv.z = __expf(sv.z - mm) * li;
            pv.w = __expf(sv.w - mm) * li;
            *reinterpret_cast<float4*>(probbase + gi) = pv;
            *reinterpret_cast<float4*>(&Ps[row*LDQ + k4]) = pv;
        }
        // stage V transposed: Vt[d][key]
        for (int i = tid; i < 64*16; i += 256) {
            int k = i >> 4, d4 = (i & 15) << 2;
            float4 v = *reinterpret_cast<const float4*>(
                vbase + (size_t)(kb + k)*DD + d4);
            Vt[(d4+0)*LDV + k] = v.x;
            Vt[(d4+1)*LDV + k] = v.y;
            Vt[(d4+2)*LDV + k] = v.z;
            Vt[(d4+3)*LDV + k] = v.w;
        }
        __syncthreads();

        #pragma unroll 2
        for (int kk = 0; kk < 8; kk++) {
            const float* p0p = &Ps[(mrow0 + grp)*LDQ + kk*8 + tig];
            const float* p1p = p0p + 8*LDQ;
            uint32_t ah[4], al[4];
            split_tf32(p0p[0], ah[0], al[0]);
            split_tf32(p1p[0], ah[1], al[1]);
            split_tf32(p0p[4], ah[2], al[2]);
            split_tf32(p1p[4], ah[3], al[3]);
            #pragma unroll
            for (int n = 0; n < 8; n++) {
                const float* vp = &Vt[(n*8 + grp)*LDV + kk*8 + tig];
                uint32_t bh0, bl0, bh1, bl1;
                split_tf32(vp[0], bh0, bl0);
                split_tf32(vp[4], bh1, bl1);
                MMA_TF32(oacc[n], ah[0], ah[1], ah[2], ah[3], bh0, bh1);
                MMA_TF32(oacc[n], ah[0], ah[1], ah[2], ah[3], bl0, bl1);
                MMA_TF32(oacc[n], al[0], al[1], al[2], al[3], bh0, bh1);
            }
        }
    }

    // ---- write O from fragments ----
    #pragma unroll
    for (int n = 0; n < 8; n++) {
        const int dcol = n*8 + 2*tig;
        #pragma unroll
        for (int hh = 0; hh < 2; hh++) {
            const int row = mrow0 + grp + 8*hh;
            *reinterpret_cast<float2*>(outbase + (size_t)row*DD + dcol) =
                make_float2(oacc[n][2*hh+0], oacc[n][2*hh+1]);
        }
    }
}

extern "C" void kernel_launch(void* const* d_in, const int* in_sizes, int n_in,
                              void* d_out, int out_size) {
    const float* q    = (const float*)d_in[0];
    const float* k    = (const float*)d_in[1];
    const float* v    = (const float*)d_in[2];
    const int*   mask = (const int*)d_in[3];

    float* out = (float*)d_out;
    const size_t n_out  = (size_t)NB*NH*SS*DD;
    const size_t n_attn = (size_t)NB*NH*SS*SS;
    float* prob = out + n_out;
    float* attn = prob + n_attn;

    const int smem_bytes = SM_FLOATS * (int)sizeof(float);   // 70,656 B
    cudaFuncSetAttribute(sdpa_mma_kernel,
                         cudaFuncAttributeMaxDynamicSharedMemorySize, smem_bytes);

    dim3 grid(SS/128, NH, NB);   // (16,16,2)
    sdpa_mma_kernel<<<grid, 256, smem_bytes>>>(q, k, v, mask, out, prob, attn);
}

// round 5
// speedup vs baseline: 1.2469x; 1.1341x over previous
#include <cuda_runtime.h>
#include <cstdint>

#define SS 2048
#define DD 64
#define NH 16
#define NB 2
#define NEGV -1000000000.0f

#define LDQ 68    // raw A-tile row stride (floats)
#define LDVT 67   // Vtmp row stride (floats), 67*... 3 coprime 32 -> conflict-free transpose reads

// smem float offsets
#define SM_QS   0                    // raw Q [128][LDQ]  (pass2: Ps)
#define SM_KPK  (128*LDQ)            // packed K [128][128] floats (pass2: Vpk [64][128] + Vtmp)
#define SM_VPK  SM_KPK
#define SM_VTMP (SM_KPK + 64*128)    // Vtmp [64][LDVT]
#define SM_M    (SM_KPK + 128*128)
#define SM_LI   (SM_M + 128)
#define SM_FLOATS (SM_LI + 128)      // 25,344 floats = 101,376 B

#define MMA_TF32(d, a0,a1,a2,a3, b0,b1) \
    asm volatile("mma.sync.aligned.m16n8k8.row.col.f32.tf32.tf32.f32 " \
        "{%0,%1,%2,%3}, {%4,%5,%6,%7}, {%8,%9}, {%0,%1,%2,%3};" \
        : "+f"((d)[0]), "+f"((d)[1]), "+f"((d)[2]), "+f"((d)[3]) \
        : "r"(a0), "r"(a1), "r"(a2), "r"(a3), "r"(b0), "r"(b1))

__device__ __forceinline__ void split_tf32(float x, uint32_t& hi, uint32_t& lo) {
    asm("cvt.rna.tf32.f32 %0, %1;" : "=r"(hi) : "f"(x));
    float l = x - __uint_as_float(hi);
    asm("cvt.rna.tf32.f32 %0, %1;" : "=r"(lo) : "f"(l));
}

// packed slot float-offset for B tiles: row*128 + (((kk ^ (row&7))<<2) | tig)*4
__device__ __forceinline__ int pk_off(int row, int kk, int tig) {
    return row*128 + ((((kk ^ (row & 7)) << 2) | tig) << 2);
}

__global__ __launch_bounds__(256, 2)
void sdpa_mma_kernel(const float* __restrict__ qg, const float* __restrict__ kg,
                     const float* __restrict__ vg, const int* __restrict__ maskg,
                     float* __restrict__ outg, float* __restrict__ probg,
                     float* __restrict__ attng)
{
    extern __shared__ float sm[];
    float* Qs   = sm + SM_QS;     // pass1 raw Q; pass2 raw P
    float* Kpk  = sm + SM_KPK;    // pass1 packed K
    float* Vpk  = sm + SM_VPK;    // pass2 packed V^T
    float* Vtmp = sm + SM_VTMP;   // pass2 raw V staging
    float* Ps   = Qs;
    float* sm_m  = sm + SM_M;
    float* sm_li = sm + SM_LI;

    const int tid = threadIdx.x;
    const int wid = tid >> 5;
    const int lid = tid & 31;
    const int grp = lid >> 2;   // 0..7
    const int tig = lid & 3;    // 0..3
    const int mrow0 = wid * 16;

    const int q0 = blockIdx.x * 128;
    const int h  = blockIdx.y;
    const int b  = blockIdx.z;
    const int bh = b*NH + h;

    const float* qbase = qg + ((size_t)bh*SS + q0) * DD;
    const float* kbase = kg + (size_t)bh*SS*DD;
    const float* vbase = vg + (size_t)bh*SS*DD;
    const int*   mbase = maskg + ((size_t)b*SS + q0) * SS;
    float* attnbase = attng + ((size_t)bh*SS + q0) * SS;
    float* probbase = probg + ((size_t)bh*SS + q0) * SS;
    float* outbase  = outg  + ((size_t)bh*SS + q0) * DD;

    // per-thread base into packed B tiles (row = n*8+grp, col-group tig)
    const float* bbase = &Kpk[grp*128 + (tig << 2)];

    // ---- stage raw Q [128][64] ----
    for (int i = tid; i < 128*16; i += 256) {
        int row = i >> 4, d4 = (i & 15) << 2;
        float4 v = *reinterpret_cast<const float4*>(qbase + (size_t)row*DD + d4);
        *reinterpret_cast<float4*>(&Qs[row*LDQ + d4]) = v;
    }

    float mrun[2] = {-1e30f, -1e30f};
    float lrun[2] = {0.0f, 0.0f};

    // ================= PASS 1 =================
    for (int kt = 0; kt < 16; kt++) {
        __syncthreads();   // prev MMA reads of Kpk done
        // stage K packed: slot (r, kk, tg) <- {hi(c0), hi(c0+4), lo(c0), lo(c0+4)}
        for (int s = tid; s < 4096; s += 256) {
            int r = s >> 5, kk = (s >> 2) & 7, tg = s & 3;
            const float* kp = kbase + (size_t)(kt*128 + r)*DD + kk*8 + tg;
            uint32_t h0, l0, h1, l1;
            split_tf32(kp[0], h0, l0);
            split_tf32(kp[4], h1, l1);
            float4 pk = make_float4(__uint_as_float(h0), __uint_as_float(h1),
                                    __uint_as_float(l0), __uint_as_float(l1));
            *reinterpret_cast<float4*>(&Kpk[pk_off(r, kk, tg)]) = pk;
        }
        __syncthreads();

        float acc[16][4];
        #pragma unroll
        for (int n = 0; n < 16; n++) {
            acc[n][0] = 0.f; acc[n][1] = 0.f; acc[n][2] = 0.f; acc[n][3] = 0.f;
        }

        #pragma unroll
        for (int kk = 0; kk < 8; kk++) {
            const float* q0p = &Qs[(mrow0 + grp)*LDQ + kk*8 + tig];
            const float* q1p = q0p + 8*LDQ;
            uint32_t ah[4], al[4];
            split_tf32(q0p[0], ah[0], al[0]);
            split_tf32(q1p[0], ah[1], al[1]);
            split_tf32(q0p[4], ah[2], al[2]);
            split_tf32(q1p[4], ah[3], al[3]);
            const float* bk = bbase + ((kk ^ grp) << 4);
            #pragma unroll
            for (int n = 0; n < 16; n++) {
                float4 bv = *reinterpret_cast<const float4*>(bk + n*1024);
                uint32_t bh0 = __float_as_uint(bv.x), bh1 = __float_as_uint(bv.y);
                uint32_t bl0 = __float_as_uint(bv.z), bl1 = __float_as_uint(bv.w);
                MMA_TF32(acc[n], ah[0], ah[1], ah[2], ah[3], bh0, bh1);
                MMA_TF32(acc[n], ah[0], ah[1], ah[2], ah[3], bl0, bl1);
                MMA_TF32(acc[n], al[0], al[1], al[2], al[3], bh0, bh1);
            }
        }

        // ---- epilogue: scale + mask + attn STG + online (m,l) ----
        float tmax[2] = {-1e30f, -1e30f};
        #pragma unroll
        for (int n = 0; n < 16; n++) {
            const int kcol = kt*128 + n*8 + 2*tig;
            #pragma unroll
            for (int hh = 0; hh < 2; hh++) {
                const int row = mrow0 + grp + 8*hh;
                int2 mm = *reinterpret_cast<const int2*>(mbase + (size_t)row*SS + kcol);
                float s0 = fmaf(acc[n][2*hh+0], 0.125f, mm.x ? 0.0f : NEGV);
                float s1 = fmaf(acc[n][2*hh+1], 0.125f, mm.y ? 0.0f : NEGV);
                *reinterpret_cast<float2*>(attnbase + (size_t)row*SS + kcol) =
                    make_float2(s0, s1);
                acc[n][2*hh+0] = s0; acc[n][2*hh+1] = s1;
                tmax[hh] = fmaxf(tmax[hh], fmaxf(s0, s1));
            }
        }
        #pragma unroll
        for (int hh = 0; hh < 2; hh++) {
            float tm = tmax[hh];
            tm = fmaxf(tm, __shfl_xor_sync(0xffffffffu, tm, 1));
            tm = fmaxf(tm, __shfl_xor_sync(0xffffffffu, tm, 2));
            float newm = fmaxf(mrun[hh], tm);
            lrun[hh] *= __expf(mrun[hh] - newm);
            float ls = 0.0f;
            #pragma unroll
            for (int n = 0; n < 16; n++) {
                ls += __expf(acc[n][2*hh+0] - newm);
                ls += __expf(acc[n][2*hh+1] - newm);
            }
            ls += __shfl_xor_sync(0xffffffffu, ls, 1);
            ls += __shfl_xor_sync(0xffffffffu, ls, 2);
            lrun[hh] += ls;
            mrun[hh] = newm;
        }
    }

    if (tig == 0) {
        #pragma unroll
        for (int hh = 0; hh < 2; hh++) {
            sm_m [mrow0 + grp + 8*hh] = mrun[hh];
            sm_li[mrow0 + grp + 8*hh] = 1.0f / lrun[hh];
        }
    }
    __syncthreads();

    // ================= PASS 2 =================
    float oacc[8][4];
    #pragma unroll
    for (int n = 0; n < 8; n++) {
        oacc[n][0] = 0.f; oacc[n][1] = 0.f; oacc[n][2] = 0.f; oacc[n][3] = 0.f;
    }

    for (int kt = 0; kt < 32; kt++) {
        const int kb = kt*64;
        __syncthreads();   // prev MMA reads of Ps/Vpk done
        // stage P = prob (re-read attn, exp, normalize) + write prob (raw A tile)
        for (int i = tid; i < 128*16; i += 256) {
            int row = i >> 4, k4 = (i & 15) << 2;
            size_t gi = (size_t)row*SS + kb + k4;
            float4 sv = *reinterpret_cast<const float4*>(attnbase + gi);
            float mm = sm_m[row], li = sm_li[row];
            float4 pv;
            pv.x = __expf(sv.x - mm) * li;
            pv.y = __expf(sv.y - mm) * li;
            pv.z = __expf(sv.z - mm) * li;
            pv.w = __expf(sv.w - mm) * li;
            *reinterpret_cast<float4*>(probbase + gi) = pv;
            *reinterpret_cast<float4*>(&Ps[row*LDQ + k4]) = pv;
        }
        // step1: raw V into Vtmp [key][d], coalesced LDG
        for (int i = tid; i < 64*16; i += 256) {
            int k = i >> 4, d4 = (i & 15) << 2;
            float4 v = *reinterpret_cast<const float4*>(
                vbase + (size_t)(kb + k)*DD + d4);
            Vtmp[k*LDVT + d4 + 0] = v.x;
            Vtmp[k*LDVT + d4 + 1] = v.y;
            Vtmp[k*LDVT + d4 + 2] = v.z;
            Vtmp[k*LDVT + d4 + 3] = v.w;
        }
        __syncthreads();
        // step2: build packed V^T: slot (d, kk, tg) <- V[key=kk*8+tg(+4)][d]
        for (int s = tid; s < 2048; s += 256) {
            int d = s >> 5, kk = (s >> 2) & 7, tg = s & 3;
            int k0 = kk*8 + tg;
            uint32_t h0, l0, h1, l1;
            split_tf32(Vtmp[k0*LDVT + d],       h0, l0);
            split_tf32(Vtmp[(k0 + 4)*LDVT + d], h1, l1);
            float4 pk = make_float4(__uint_as_float(h0), __uint_as_float(h1),
                                    __uint_as_float(l0), __uint_as_float(l1));
            *reinterpret_cast<float4*>(&Vpk[pk_off(d, kk, tg)]) = pk;
        }
        __syncthreads();

        #pragma unroll
        for (int kk = 0; kk < 8; kk++) {
            const float* p0p = &Ps[(mrow0 + grp)*LDQ + kk*8 + tig];
            const float* p1p = p0p + 8*LDQ;
            uint32_t ah[4], al[4];
            split_tf32(p0p[0], ah[0], al[0]);
            split_tf32(p1p[0], ah[1], al[1]);
            split_tf32(p0p[4], ah[2], al[2]);
            split_tf32(p1p[4], ah[3], al[3]);
            const float* bk = &Vpk[grp*128 + (tig << 2)] + ((kk ^ grp) << 4);
            #pragma unroll
            for (int n = 0; n < 8; n++) {
                float4 bv = *reinterpret_cast<const float4*>(bk + n*1024);
                uint32_t bh0 = __float_as_uint(bv.x), bh1 = __float_as_uint(bv.y);
                uint32_t bl0 = __float_as_uint(bv.z), bl1 = __float_as_uint(bv.w);
                MMA_TF32(oacc[n], ah[0], ah[1], ah[2], ah[3], bh0, bh1);
                MMA_TF32(oacc[n], ah[0], ah[1], ah[2], ah[3], bl0, bl1);
                MMA_TF32(oacc[n], al[0], al[1], al[2], al[3], bh0, bh1);
            }
        }
    }

    // ---- write O from fragments ----
    #pragma unroll
    for (int n = 0; n < 8; n++) {
        const int dcol = n*8 + 2*tig;
        #pragma unroll
        for (int hh = 0; hh < 2; hh++) {
            const int row = mrow0 + grp + 8*hh;
            *reinterpret_cast<float2*>(outbase + (size_t)row*DD + dcol) =
                make_float2(oacc[n][2*hh+0], oacc[n][2*hh+1]);
        }
    }
}

extern "C" void kernel_launch(void* const* d_in, const int* in_sizes, int n_in,
                              void* d_out, int out_size) {
    const float* q    = (const float*)d_in[0];
    const float* k    = (const float*)d_in[1];
    const float* v    = (const float*)d_in[2];
    const int*   mask = (const int*)d_in[3];

    float* out = (float*)d_out;
    const size_t n_out  = (size_t)NB*NH*SS*DD;
    const size_t n_attn = (size_t)NB*NH*SS*SS;
    float* prob = out + n_out;
    float* attn = prob + n_attn;

    const int smem_bytes = SM_FLOATS * (int)sizeof(float);   // 101,376 B
    cudaFuncSetAttribute(sdpa_mma_kernel,
                         cudaFuncAttributeMaxDynamicSharedMemorySize, smem_bytes);

    dim3 grid(SS/128, NH, NB);   // (16,16,2)
    sdpa_mma_kernel<<<grid, 256, smem_bytes>>>(q, k, v, mask, out, prob, attn);
}

// round 6
// speedup vs baseline: 1.4481x; 1.1614x over previous
#include <cuda_runtime.h>
#include <cstdint>

#define SS 2048
#define DD 64
#define NH 16
#define NB 2
#define NEGV -1000000000.0f
#define LDQ 68

// smem float offsets (main kernel)
#define SM_QS   0                 // raw Q [128][LDQ]; pass2: Ps
#define SM_DB   (128*LDQ)         // double buffer: 2 x 8192 floats (32KB tiles)
#define SM_M    (SM_DB + 16384)
#define SM_LI   (SM_M + 128)
#define SM_FLOATS (SM_LI + 128)   // 25,344 floats = 101,376 B

// packed scratch: [bh][tile64][8192 floats]
__device__ float    g_kpk[(size_t)NB*NH*32*8192];
__device__ float    g_vpk[(size_t)NB*NH*32*8192];
__device__ unsigned g_mbits[(size_t)NB*SS*64];

#define MMA_TF32(d, a0,a1,a2,a3, b0,b1) \
    asm volatile("mma.sync.aligned.m16n8k8.row.col.f32.tf32.tf32.f32 " \
        "{%0,%1,%2,%3}, {%4,%5,%6,%7}, {%8,%9}, {%0,%1,%2,%3};" \
        : "+f"((d)[0]), "+f"((d)[1]), "+f"((d)[2]), "+f"((d)[3]) \
        : "r"(a0), "r"(a1), "r"(a2), "r"(a3), "r"(b0), "r"(b1))

__device__ __forceinline__ void split_tf32(float x, uint32_t& hi, uint32_t& lo) {
    asm("cvt.rna.tf32.f32 %0, %1;" : "=r"(hi) : "f"(x));
    float l = x - __uint_as_float(hi);
    asm("cvt.rna.tf32.f32 %0, %1;" : "=r"(lo) : "f"(l));
}
__device__ __forceinline__ uint32_t smem_u32(const void* p) {
    uint32_t a;
    asm("{ .reg .u64 t; cvta.to.shared.u64 t, %1; cvt.u32.u64 %0, t; }" : "=r"(a) : "l"(p));
    return a;
}
// packed slot float-offset: row*128 + (((kk ^ (row&7))<<2) | tig)*4
__device__ __forceinline__ int pk_off(int row, int kk, int tig) {
    return row*128 + ((((kk ^ (row & 7)) << 2) | tig) << 2);
}
__device__ __forceinline__ void cp16(uint32_t dst, const float* src) {
    asm volatile("cp.async.cg.shared.global [%0], [%1], 16;" :: "r"(dst), "l"(src));
}
__device__ __forceinline__ void cp_commit() { asm volatile("cp.async.commit_group;"); }
__device__ __forceinline__ void cp_wait1()  { asm volatile("cp.async.wait_group 1;" ::: "memory"); }
__device__ __forceinline__ void cp_wait0()  { asm volatile("cp.async.wait_group 0;" ::: "memory"); }

// copy one 32KB packed tile (2048 float4) into smem
__device__ __forceinline__ void cp_tile(uint32_t dst_byte, const float* src, int tid) {
    #pragma unroll
    for (int j = 0; j < 8; j++) {
        int e = tid + j*256;
        cp16(dst_byte + e*16, src + e*4);
    }
}

// ---------------- prologue kernels ----------------
__global__ void pack_k_kernel(const float* __restrict__ kg) {
    const int kt = blockIdx.x, h = blockIdx.y, b = blockIdx.z;
    const int bh = b*NH + h;
    const float* base = kg + ((size_t)bh*SS + kt*64) * DD;
    float* out = g_kpk + ((size_t)bh*32 + kt) * 8192;
    for (int s = threadIdx.x; s < 2048; s += 256) {
        int r = s >> 5, kk = (s >> 2) & 7, tg = s & 3;
        const float* kp = base + (size_t)r*DD + kk*8 + tg;
        uint32_t h0, l0, h1, l1;
        split_tf32(kp[0], h0, l0);
        split_tf32(kp[4], h1, l1);
        *reinterpret_cast<float4*>(out + pk_off(r, kk, tg)) =
            make_float4(__uint_as_float(h0), __uint_as_float(h1),
                        __uint_as_float(l0), __uint_as_float(l1));
    }
}

__global__ void pack_v_kernel(const float* __restrict__ vg) {
    __shared__ float Vs[64*65];
    const int kt = blockIdx.x, h = blockIdx.y, b = blockIdx.z;
    const int bh = b*NH + h;
    const float* base = vg + ((size_t)bh*SS + kt*64) * DD;
    float* out = g_vpk + ((size_t)bh*32 + kt) * 8192;
    for (int i = threadIdx.x; i < 64*16; i += 256) {
        int k = i >> 4, d4 = (i & 15) << 2;
        float4 v = *reinterpret_cast<const float4*>(base + (size_t)k*DD + d4);
        Vs[k*65 + d4 + 0] = v.x; Vs[k*65 + d4 + 1] = v.y;
        Vs[k*65 + d4 + 2] = v.z; Vs[k*65 + d4 + 3] = v.w;
    }
    __syncthreads();
    for (int s = threadIdx.x; s < 2048; s += 256) {
        int d = s >> 5, kk = (s >> 2) & 7, tg = s & 3;
        int k0 = kk*8 + tg;
        uint32_t h0, l0, h1, l1;
        split_tf32(Vs[k0*65 + d],       h0, l0);
        split_tf32(Vs[(k0 + 4)*65 + d], h1, l1);
        *reinterpret_cast<float4*>(out + pk_off(d, kk, tg)) =
            make_float4(__uint_as_float(h0), __uint_as_float(h1),
                        __uint_as_float(l0), __uint_as_float(l1));
    }
}

__global__ void pack_mask_kernel(const int* __restrict__ maskg) {
    int gt = blockIdx.x*256 + threadIdx.x;
    int widx = gt >> 5;
    int lane = gt & 31;
    int w = widx & 63;
    int row = (widx >> 6) & (SS - 1);
    int b = widx >> 17;
    int c = w*32 + lane;
    unsigned nz = maskg[((size_t)b*SS + row)*SS + c] != 0;
    unsigned bits = __ballot_sync(0xffffffffu, nz);
    if (lane == 0) g_mbits[widx] = bits;
}

// ---------------- main kernel ----------------
__global__ __launch_bounds__(256, 2)
void sdpa_main_kernel(const float* __restrict__ qg,
                      float* __restrict__ outg, float* __restrict__ probg,
                      float* __restrict__ attng)
{
    extern __shared__ float sm[];
    float* Qs = sm + SM_QS;
    float* Ps = Qs;
    float* sm_m  = sm + SM_M;
    float* sm_li = sm + SM_LI;
    const uint32_t db_byte = smem_u32(sm + SM_DB);

    const int tid = threadIdx.x;
    const int wid = tid >> 5;
    const int lid = tid & 31;
    const int grp = lid >> 2;
    const int tig = lid & 3;
    const int mrow0 = wid * 16;

    const int q0 = blockIdx.x * 128;
    const int h  = blockIdx.y;
    const int b  = blockIdx.z;
    const int bh = b*NH + h;

    const float* qbase = qg + ((size_t)bh*SS + q0) * DD;
    float* attnbase = attng + ((size_t)bh*SS + q0) * SS;
    float* probbase = probg + ((size_t)bh*SS + q0) * SS;
    float* outbase  = outg  + ((size_t)bh*SS + q0) * DD;
    const float* kpk = g_kpk + (size_t)bh*32*8192;
    const float* vpk = g_vpk + (size_t)bh*32*8192;
    const unsigned* mrow0bits = g_mbits + ((size_t)b*SS + q0)*64;

    // stage raw Q
    for (int i = tid; i < 128*16; i += 256) {
        int row = i >> 4, d4 = (i & 15) << 2;
        float4 v = *reinterpret_cast<const float4*>(qbase + (size_t)row*DD + d4);
        *reinterpret_cast<float4*>(&Qs[row*LDQ + d4]) = v;
    }

    // prefetch tile 0
    cp_tile(db_byte, kpk, tid);
    cp_commit();

    float mrun[2] = {-1e30f, -1e30f};
    float lrun[2] = {0.0f, 0.0f};

    // ================= PASS 1 =================
    for (int t = 0; t < 32; t++) {
        __syncthreads();   // all warps done reading buf[(t+1)&1] from iter t-1
        if (t < 31) {
            cp_tile(db_byte + ((t+1)&1)*32768, kpk + (size_t)(t+1)*8192, tid);
            cp_commit();
            cp_wait1();
        } else {
            cp_wait0();
        }
        __syncthreads();   // buf[t&1] ready for all

        const float* kbuf = sm + SM_DB + (t&1)*8192;
        const float* bbase = kbuf + grp*128 + (tig << 2);

        float acc[8][4];
        #pragma unroll
        for (int n = 0; n < 8; n++) {
            acc[n][0] = 0.f; acc[n][1] = 0.f; acc[n][2] = 0.f; acc[n][3] = 0.f;
        }

        #pragma unroll
        for (int kk = 0; kk < 8; kk++) {
            const float* q0p = &Qs[(mrow0 + grp)*LDQ + kk*8 + tig];
            const float* q1p = q0p + 8*LDQ;
            uint32_t ah[4], al[4];
            split_tf32(q0p[0], ah[0], al[0]);
            split_tf32(q1p[0], ah[1], al[1]);
            split_tf32(q0p[4], ah[2], al[2]);
            split_tf32(q1p[4], ah[3], al[3]);
            const float* bk = bbase + ((kk ^ grp) << 4);
            #pragma unroll
            for (int n = 0; n < 8; n++) {
                float4 bv = *reinterpret_cast<const float4*>(bk + n*1024);
                uint32_t bh0 = __float_as_uint(bv.x), bh1 = __float_as_uint(bv.y);
                uint32_t bl0 = __float_as_uint(bv.z), bl1 = __float_as_uint(bv.w);
                MMA_TF32(acc[n], ah[0], ah[1], ah[2], ah[3], bh0, bh1);
                MMA_TF32(acc[n], ah[0], ah[1], ah[2], ah[3], bl0, bl1);
                MMA_TF32(acc[n], al[0], al[1], al[2], al[3], bh0, bh1);
            }
        }

        // ---- epilogue: bit-mask + scale + attn STG + online (m,l) ----
        const int r0 = mrow0 + grp, r1 = r0 + 8;
        uint2 w0 = *reinterpret_cast<const uint2*>(mrow0bits + (size_t)r0*64 + t*2);
        uint2 w1 = *reinterpret_cast<const uint2*>(mrow0bits + (size_t)r1*64 + t*2);
        float tmax[2] = {-1e30f, -1e30f};
        #pragma unroll
        for (int n = 0; n < 8; n++) {
            const int c = n*8 + 2*tig;
            const unsigned word0 = (n < 4) ? w0.x : w0.y;
            const unsigned word1 = (n < 4) ? w1.x : w1.y;
            const int sh = c & 31;
            float s0 = fmaf(acc[n][0], 0.125f, ((word0 >> sh) & 1u) ? 0.0f : NEGV);
            float s1 = fmaf(acc[n][1], 0.125f, ((word0 >> (sh+1)) & 1u) ? 0.0f : NEGV);
            float s2 = fmaf(acc[n][2], 0.125f, ((word1 >> sh) & 1u) ? 0.0f : NEGV);
            float s3 = fmaf(acc[n][3], 0.125f, ((word1 >> (sh+1)) & 1u) ? 0.0f : NEGV);
            const int kcol = t*64 + c;
            *reinterpret_cast<float2*>(attnbase + (size_t)r0*SS + kcol) = make_float2(s0, s1);
            *reinterpret_cast<float2*>(attnbase + (size_t)r1*SS + kcol) = make_float2(s2, s3);
            acc[n][0] = s0; acc[n][1] = s1; acc[n][2] = s2; acc[n][3] = s3;
            tmax[0] = fmaxf(tmax[0], fmaxf(s0, s1));
            tmax[1] = fmaxf(tmax[1], fmaxf(s2, s3));
        }
        #pragma unroll
        for (int hh = 0; hh < 2; hh++) {
            float tm = tmax[hh];
            tm = fmaxf(tm, __shfl_xor_sync(0xffffffffu, tm, 1));
            tm = fmaxf(tm, __shfl_xor_sync(0xffffffffu, tm, 2));
            float newm = fmaxf(mrun[hh], tm);
            lrun[hh] *= __expf(mrun[hh] - newm);
            float ls = 0.0f;
            #pragma unroll
            for (int n = 0; n < 8; n++) {
                ls += __expf(acc[n][2*hh+0] - newm);
                ls += __expf(acc[n][2*hh+1] - newm);
            }
            ls += __shfl_xor_sync(0xffffffffu, ls, 1);
            ls += __shfl_xor_sync(0xffffffffu, ls, 2);
            lrun[hh] += ls;
            mrun[hh] = newm;
        }
    }

    if (tig == 0) {
        sm_m [mrow0 + grp]     = mrun[0];
        sm_li[mrow0 + grp]     = 1.0f / lrun[0];
        sm_m [mrow0 + grp + 8] = mrun[1];
        sm_li[mrow0 + grp + 8] = 1.0f / lrun[1];
    }
    __syncthreads();

    // prefetch V tile 0 (buf0 safe: all pass-1 reads done at the sync above)
    cp_tile(db_byte, vpk, tid);
    cp_commit();

    // ================= PASS 2 =================
    float oacc[8][4];
    #pragma unroll
    for (int n = 0; n < 8; n++) {
        oacc[n][0] = 0.f; oacc[n][1] = 0.f; oacc[n][2] = 0.f; oacc[n][3] = 0.f;
    }

    for (int t = 0; t < 32; t++) {
        __syncthreads();   // prev MMA reads of Ps and buf[(t+1)&1] done
        if (t < 31) {
            cp_tile(db_byte + ((t+1)&1)*32768, vpk + (size_t)(t+1)*8192, tid);
            cp_commit();
        }
        // stage Ps = prob (re-read attn, exp, normalize) + write prob
        const int kb = t*64;
        for (int i = tid; i < 128*16; i += 256) {
            int row = i >> 4, k4 = (i & 15) << 2;
            size_t gi = (size_t)row*SS + kb + k4;
            float4 sv = *reinterpret_cast<const float4*>(attnbase + gi);
            float mm = sm_m[row], li = sm_li[row];
            float4 pv;
            pv.x = __expf(sv.x - mm) * li;
            pv.y = __expf(sv.y - mm) * li;
            pv.z = __expf(sv.z - mm) * li;
            pv.w = __expf(sv.w - mm) * li;
            *reinterpret_cast<float4*>(probbase + gi) = pv;
            *reinterpret_cast<float4*>(&Ps[row*LDQ + k4]) = pv;
        }
        if (t < 31) cp_wait1(); else cp_wait0();
        __syncthreads();

        const float* vbuf = sm + SM_DB + (t&1)*8192;
        #pragma unroll
        for (int kk = 0; kk < 8; kk++) {
            const float* p0p = &Ps[(mrow0 + grp)*LDQ + kk*8 + tig];
            const float* p1p = p0p + 8*LDQ;
            uint32_t ah[4], al[4];
            split_tf32(p0p[0], ah[0], al[0]);
            split_tf32(p1p[0], ah[1], al[1]);
            split_tf32(p0p[4], ah[2], al[2]);
            split_tf32(p1p[4], ah[3], al[3]);
            const float* bk = vbuf + grp*128 + (tig << 2) + ((kk ^ grp) << 4);
            #pragma unroll
            for (int n = 0; n < 8; n++) {
                float4 bv = *reinterpret_cast<const float4*>(bk + n*1024);
                uint32_t bh0 = __float_as_uint(bv.x), bh1 = __float_as_uint(bv.y);
                uint32_t bl0 = __float_as_uint(bv.z), bl1 = __float_as_uint(bv.w);
                MMA_TF32(oacc[n], ah[0], ah[1], ah[2], ah[3], bh0, bh1);
                MMA_TF32(oacc[n], ah[0], ah[1], ah[2], ah[3], bl0, bl1);
                MMA_TF32(oacc[n], al[0], al[1], al[2], al[3], bh0, bh1);
            }
        }
    }

    // ---- write O ----
    #pragma unroll
    for (int n = 0; n < 8; n++) {
        const int dcol = n*8 + 2*tig;
        *reinterpret_cast<float2*>(outbase + (size_t)(mrow0 + grp)*DD + dcol) =
            make_float2(oacc[n][0], oacc[n][1]);
        *reinterpret_cast<float2*>(outbase + (size_t)(mrow0 + grp + 8)*DD + dcol) =
            make_float2(oacc[n][2], oacc[n][3]);
    }
}

extern "C" void kernel_launch(void* const* d_in, const int* in_sizes, int n_in,
                              void* d_out, int out_size) {
    const float* q    = (const float*)d_in[0];
    const float* k    = (const float*)d_in[1];
    const float* v    = (const float*)d_in[2];
    const int*   mask = (const int*)d_in[3];

    float* out = (float*)d_out;
    const size_t n_out  = (size_t)NB*NH*SS*DD;
    const size_t n_attn = (size_t)NB*NH*SS*SS;
    float* prob = out + n_out;
    float* attn = prob + n_attn;

    dim3 pgrid(32, NH, NB);
    pack_k_kernel<<<pgrid, 256>>>(k);
    pack_v_kernel<<<pgrid, 256>>>(v);
    pack_mask_kernel<<<(NB*SS*64*32)/256, 256>>>(mask);

    const int smem_bytes = SM_FLOATS * (int)sizeof(float);   // 101,376 B
    cudaFuncSetAttribute(sdpa_main_kernel,
                         cudaFuncAttributeMaxDynamicSharedMemorySize, smem_bytes);
    dim3 grid(SS/128, NH, NB);
    sdpa_main_kernel<<<grid, 256, smem_bytes>>>(q, out, prob, attn);
}

// round 7
// speedup vs baseline: 1.6007x; 1.1054x over previous
#include <cuda_runtime.h>
#include <cstdint>

#define SS 2048
#define DD 64
#define NH 16
#define NB 2
#define NEGV -1000000000.0f
#define LDQ 68

// ---- kernel1 smem (floats) ----
#define K1_QS 0                    // raw Q [128][LDQ]
#define K1_DB (128*LDQ)            // K db: 2 x 4096 floats (16KB tiles)
#define K1_MB (K1_DB + 8192)       // mask db: 2 x 128 words
#define K1_FLOATS (K1_MB + 256)    // 17,152 floats = 68,608 B

// ---- kernel2 smem (floats) ----
#define K2_PS 0                    // Ps [128][LDQ]
#define K2_DB (128*LDQ)            // V db: 2 x 4096 floats
#define K2_M  (K2_DB + 8192)
#define K2_LI (K2_M + 128)
#define K2_FLOATS (K2_LI + 128)    // 17,152 floats = 68,608 B

// packed scratch: 64 tiles of 4096 floats per bh
__device__ float    g_kpk[(size_t)NB*NH*64*4096];
__device__ float    g_vpk[(size_t)NB*NH*64*4096];
__device__ unsigned g_mbits[(size_t)NB*SS*64];
__device__ float    g_ml[(size_t)NB*NH*SS*2];

#define MMA_TF32(d, a0,a1,a2,a3, b0,b1) \
    asm volatile("mma.sync.aligned.m16n8k8.row.col.f32.tf32.tf32.f32 " \
        "{%0,%1,%2,%3}, {%4,%5,%6,%7}, {%8,%9}, {%0,%1,%2,%3};" \
        : "+f"((d)[0]), "+f"((d)[1]), "+f"((d)[2]), "+f"((d)[3]) \
        : "r"(a0), "r"(a1), "r"(a2), "r"(a3), "r"(b0), "r"(b1))

__device__ __forceinline__ void split_tf32(float x, uint32_t& hi, uint32_t& lo) {
    asm("cvt.rna.tf32.f32 %0, %1;" : "=r"(hi) : "f"(x));
    float l = x - __uint_as_float(hi);
    asm("cvt.rna.tf32.f32 %0, %1;" : "=r"(lo) : "f"(l));
}
__device__ __forceinline__ uint32_t smem_u32(const void* p) {
    uint32_t a;
    asm("{ .reg .u64 t; cvta.to.shared.u64 t, %1; cvt.u32.u64 %0, t; }" : "=r"(a) : "l"(p));
    return a;
}
// K-packed slot float-offset (rows = keys, 128 floats/row):
// row*128 + (((kk ^ (row&7))<<2)|tig)*4,  kk in 0..7
__device__ __forceinline__ int pk_off_k(int row, int kk, int tig) {
    return row*128 + ((((kk ^ (row & 7)) << 2) | tig) << 2);
}
// V-packed slot float-offset (rows = d, 64 floats/row): kk in 0..3
__device__ __forceinline__ int pk_off_v(int row, int kk, int tig) {
    return row*64 + ((((kk ^ (row & 3)) << 2) | tig) << 2);
}
__device__ __forceinline__ void cp16(uint32_t dst, const void* src) {
    asm volatile("cp.async.cg.shared.global [%0], [%1], 16;" :: "r"(dst), "l"(src));
}
__device__ __forceinline__ void cp4(uint32_t dst, const void* src) {
    asm volatile("cp.async.ca.shared.global [%0], [%1], 4;" :: "r"(dst), "l"(src));
}
__device__ __forceinline__ void cp_commit() { asm volatile("cp.async.commit_group;"); }
__device__ __forceinline__ void cp_wait1()  { asm volatile("cp.async.wait_group 1;" ::: "memory"); }
__device__ __forceinline__ void cp_wait0()  { asm volatile("cp.async.wait_group 0;" ::: "memory"); }

// copy one 16KB packed tile (1024 float4) into smem
__device__ __forceinline__ void cp_tile32(uint32_t dst_byte, const float* src, int tid) {
    #pragma unroll
    for (int j = 0; j < 4; j++) {
        int e = tid + j*256;
        cp16(dst_byte + e*16, src + e*4);
    }
}

// ---------------- prologue kernels ----------------
__global__ void pack_k_kernel(const float* __restrict__ kg) {
    const int kt = blockIdx.x, h = blockIdx.y, b = blockIdx.z;
    const int bh = b*NH + h;
    const float* base = kg + ((size_t)bh*SS + kt*32) * DD;
    float* out = g_kpk + ((size_t)bh*64 + kt) * 4096;
    for (int s = threadIdx.x; s < 1024; s += 256) {
        int r = s >> 5, kk = (s >> 2) & 7, tg = s & 3;
        const float* kp = base + (size_t)r*DD + kk*8 + tg;
        uint32_t h0, l0, h1, l1;
        split_tf32(kp[0], h0, l0);
        split_tf32(kp[4], h1, l1);
        *reinterpret_cast<float4*>(out + pk_off_k(r, kk, tg)) =
            make_float4(__uint_as_float(h0), __uint_as_float(h1),
                        __uint_as_float(l0), __uint_as_float(l1));
    }
}

__global__ void pack_v_kernel(const float* __restrict__ vg) {
    __shared__ float Vs[32*65];
    const int kt = blockIdx.x, h = blockIdx.y, b = blockIdx.z;
    const int bh = b*NH + h;
    const float* base = vg + ((size_t)bh*SS + kt*32) * DD;
    float* out = g_vpk + ((size_t)bh*64 + kt) * 4096;
    for (int i = threadIdx.x; i < 32*16; i += 256) {
        int k = i >> 4, d4 = (i & 15) << 2;
        float4 v = *reinterpret_cast<const float4*>(base + (size_t)k*DD + d4);
        Vs[k*65 + d4 + 0] = v.x; Vs[k*65 + d4 + 1] = v.y;
        Vs[k*65 + d4 + 2] = v.z; Vs[k*65 + d4 + 3] = v.w;
    }
    __syncthreads();
    for (int s = threadIdx.x; s < 1024; s += 256) {
        int d = s >> 4, kk = (s >> 2) & 3, tg = s & 3;
        int k0 = kk*8 + tg;
        uint32_t h0, l0, h1, l1;
        split_tf32(Vs[k0*65 + d],       h0, l0);
        split_tf32(Vs[(k0 + 4)*65 + d], h1, l1);
        *reinterpret_cast<float4*>(out + pk_off_v(d, kk, tg)) =
            make_float4(__uint_as_float(h0), __uint_as_float(h1),
                        __uint_as_float(l0), __uint_as_float(l1));
    }
}

__global__ void pack_mask_kernel(const int* __restrict__ maskg) {
    int gt = blockIdx.x*256 + threadIdx.x;
    int widx = gt >> 5;
    int lane = gt & 31;
    int w = widx & 63;
    int row = (widx >> 6) & (SS - 1);
    int b = widx >> 17;
    int c = w*32 + lane;
    unsigned nz = maskg[((size_t)b*SS + row)*SS + c] != 0;
    unsigned bits = __ballot_sync(0xffffffffu, nz);
    if (lane == 0) g_mbits[widx] = bits;
}

// ---------------- pass 1: scores + attn + (m, 1/l) ----------------
__global__ __launch_bounds__(256, 3)
void sdpa_pass1_kernel(const float* __restrict__ qg, float* __restrict__ attng)
{
    extern __shared__ float sm[];
    float* Qs = sm + K1_QS;
    unsigned* maskbuf = reinterpret_cast<unsigned*>(sm + K1_MB);
    const uint32_t db_byte = smem_u32(sm + K1_DB);
    const uint32_t mb_byte = smem_u32(sm + K1_MB);

    const int tid = threadIdx.x;
    const int wid = tid >> 5;
    const int lid = tid & 31;
    const int grp = lid >> 2;
    const int tig = lid & 3;
    const int mrow0 = wid * 16;

    const int q0 = blockIdx.x * 128;
    const int h  = blockIdx.y;
    const int b  = blockIdx.z;
    const int bh = b*NH + h;

    const float* qbase = qg + ((size_t)bh*SS + q0) * DD;
    float* attnbase = attng + ((size_t)bh*SS + q0) * SS;
    const float* kpk = g_kpk + (size_t)bh*64*4096;
    const unsigned* mbits = g_mbits + ((size_t)b*SS + q0)*64;

    // stage raw Q
    for (int i = tid; i < 128*16; i += 256) {
        int row = i >> 4, d4 = (i & 15) << 2;
        float4 v = *reinterpret_cast<const float4*>(qbase + (size_t)row*DD + d4);
        *reinterpret_cast<float4*>(&Qs[row*LDQ + d4]) = v;
    }

    // prefetch tile 0 (K + mask)
    cp_tile32(db_byte, kpk, tid);
    if (tid < 128) cp4(mb_byte + tid*4, mbits + (size_t)tid*64);
    cp_commit();

    float mrun[2] = {-1e30f, -1e30f};
    float lrun[2] = {0.0f, 0.0f};

    for (int t = 0; t < 64; t++) {
        __syncthreads();
        if (t < 63) {
            cp_tile32(db_byte + ((t+1)&1)*16384, kpk + (size_t)(t+1)*4096, tid);
            if (tid < 128)
                cp4(mb_byte + ((t+1)&1)*512 + tid*4, mbits + (size_t)tid*64 + (t+1));
            cp_commit();
            cp_wait1();
        } else {
            cp_wait0();
        }
        __syncthreads();

        const float* kbuf = sm + K1_DB + (t&1)*4096;
        const float* bbase = kbuf + grp*128 + (tig << 2);

        float acc[4][4];
        #pragma unroll
        for (int n = 0; n < 4; n++) {
            acc[n][0] = 0.f; acc[n][1] = 0.f; acc[n][2] = 0.f; acc[n][3] = 0.f;
        }

        #pragma unroll
        for (int kk = 0; kk < 8; kk++) {
            const float* q0p = &Qs[(mrow0 + grp)*LDQ + kk*8 + tig];
            const float* q1p = q0p + 8*LDQ;
            uint32_t ah[4], al[4];
            split_tf32(q0p[0], ah[0], al[0]);
            split_tf32(q1p[0], ah[1], al[1]);
            split_tf32(q0p[4], ah[2], al[2]);
            split_tf32(q1p[4], ah[3], al[3]);
            const float* bk = bbase + ((kk ^ grp) << 4);
            #pragma unroll
            for (int n = 0; n < 4; n++) {
                float4 bv = *reinterpret_cast<const float4*>(bk + n*1024);
                uint32_t bh0 = __float_as_uint(bv.x), bh1 = __float_as_uint(bv.y);
                uint32_t bl0 = __float_as_uint(bv.z), bl1 = __float_as_uint(bv.w);
                MMA_TF32(acc[n], ah[0], ah[1], ah[2], ah[3], bh0, bh1);
                MMA_TF32(acc[n], ah[0], ah[1], ah[2], ah[3], bl0, bl1);
                MMA_TF32(acc[n], al[0], al[1], al[2], al[3], bh0, bh1);
            }
        }

        // epilogue: mask bits (smem) + scale + attn STG + online (m,l)
        const int r0 = mrow0 + grp, r1 = r0 + 8;
        const unsigned word0 = maskbuf[(t&1)*128 + r0];
        const unsigned word1 = maskbuf[(t&1)*128 + r1];
        float tmax[2] = {-1e30f, -1e30f};
        #pragma unroll
        for (int n = 0; n < 4; n++) {
            const int c = n*8 + 2*tig;
            float s0 = fmaf(acc[n][0], 0.125f, ((word0 >> c) & 1u) ? 0.0f : NEGV);
            float s1 = fmaf(acc[n][1], 0.125f, ((word0 >> (c+1)) & 1u) ? 0.0f : NEGV);
            float s2 = fmaf(acc[n][2], 0.125f, ((word1 >> c) & 1u) ? 0.0f : NEGV);
            float s3 = fmaf(acc[n][3], 0.125f, ((word1 >> (c+1)) & 1u) ? 0.0f : NEGV);
            const int kcol = t*32 + c;
            *reinterpret_cast<float2*>(attnbase + (size_t)r0*SS + kcol) = make_float2(s0, s1);
            *reinterpret_cast<float2*>(attnbase + (size_t)r1*SS + kcol) = make_float2(s2, s3);
            acc[n][0] = s0; acc[n][1] = s1; acc[n][2] = s2; acc[n][3] = s3;
            tmax[0] = fmaxf(tmax[0], fmaxf(s0, s1));
            tmax[1] = fmaxf(tmax[1], fmaxf(s2, s3));
        }
        #pragma unroll
        for (int hh = 0; hh < 2; hh++) {
            float tm = tmax[hh];
            tm = fmaxf(tm, __shfl_xor_sync(0xffffffffu, tm, 1));
            tm = fmaxf(tm, __shfl_xor_sync(0xffffffffu, tm, 2));
            float newm = fmaxf(mrun[hh], tm);
            lrun[hh] *= __expf(mrun[hh] - newm);
            float ls = 0.0f;
            #pragma unroll
            for (int n = 0; n < 4; n++) {
                ls += __expf(acc[n][2*hh+0] - newm);
                ls += __expf(acc[n][2*hh+1] - newm);
            }
            ls += __shfl_xor_sync(0xffffffffu, ls, 1);
            ls += __shfl_xor_sync(0xffffffffu, ls, 2);
            lrun[hh] += ls;
            mrun[hh] = newm;
        }
    }

    if (tig == 0) {
        float* mlb = g_ml + ((size_t)bh*SS + q0)*2;
        mlb[(mrow0 + grp)*2 + 0]     = mrun[0];
        mlb[(mrow0 + grp)*2 + 1]     = 1.0f / lrun[0];
        mlb[(mrow0 + grp + 8)*2 + 0] = mrun[1];
        mlb[(mrow0 + grp + 8)*2 + 1] = 1.0f / lrun[1];
    }
}

// ---------------- pass 2: prob + O ----------------
__global__ __launch_bounds__(256, 3)
void sdpa_pass2_kernel(float* __restrict__ outg, float* __restrict__ probg,
                       const float* __restrict__ attng)
{
    extern __shared__ float sm[];
    float* Ps = sm + K2_PS;
    float* sm_m  = sm + K2_M;
    float* sm_li = sm + K2_LI;
    const uint32_t db_byte = smem_u32(sm + K2_DB);

    const int tid = threadIdx.x;
    const int wid = tid >> 5;
    const int lid = tid & 31;
    const int grp = lid >> 2;
    const int tig = lid & 3;
    const int mrow0 = wid * 16;

    const int q0 = blockIdx.x * 128;
    const int h  = blockIdx.y;
    const int b  = blockIdx.z;
    const int bh = b*NH + h;

    const float* attnbase = attng + ((size_t)bh*SS + q0) * SS;
    float* probbase = probg + ((size_t)bh*SS + q0) * SS;
    float* outbase  = outg  + ((size_t)bh*SS + q0) * DD;
    const float* vpk = g_vpk + (size_t)bh*64*4096;

    if (tid < 128) {
        const float* mlb = g_ml + ((size_t)bh*SS + q0)*2;
        sm_m [tid] = mlb[tid*2 + 0];
        sm_li[tid] = mlb[tid*2 + 1];
    }

    cp_tile32(db_byte, vpk, tid);
    cp_commit();
    __syncthreads();   // m/li visible

    float oacc[8][4];
    #pragma unroll
    for (int n = 0; n < 8; n++) {
        oacc[n][0] = 0.f; oacc[n][1] = 0.f; oacc[n][2] = 0.f; oacc[n][3] = 0.f;
    }

    for (int t = 0; t < 64; t++) {
        __syncthreads();   // all warps done with vbuf[(t+1)&1]
        if (t < 63) {
            cp_tile32(db_byte + ((t+1)&1)*16384, vpk + (size_t)(t+1)*4096, tid);
            cp_commit();
            cp_wait1();
        } else {
            cp_wait0();
        }
        __syncthreads();   // vbuf[t&1] ready

        // warp-private staging of Ps rows mrow0..mrow0+15, 32 cols
        #pragma unroll
        for (int j = 0; j < 4; j++) {
            int idx = j*32 + lid;
            int row = mrow0 + (idx >> 3);
            int c4  = (idx & 7) << 2;
            size_t gi = (size_t)row*SS + t*32 + c4;
            float4 sv = *reinterpret_cast<const float4*>(attnbase + gi);
            float mm = sm_m[row], li = sm_li[row];
            float4 pv;
            pv.x = __expf(sv.x - mm) * li;
            pv.y = __expf(sv.y - mm) * li;
            pv.z = __expf(sv.z - mm) * li;
            pv.w = __expf(sv.w - mm) * li;
            *reinterpret_cast<float4*>(probbase + gi) = pv;
            *reinterpret_cast<float4*>(&Ps[row*LDQ + c4]) = pv;
        }
        __syncwarp();

        const float* vbuf = sm + K2_DB + (t&1)*4096;
        #pragma unroll
        for (int kk = 0; kk < 4; kk++) {
            const float* p0p = &Ps[(mrow0 + grp)*LDQ + kk*8 + tig];
            const float* p1p = p0p + 8*LDQ;
            uint32_t ah[4], al[4];
            split_tf32(p0p[0], ah[0], al[0]);
            split_tf32(p1p[0], ah[1], al[1]);
            split_tf32(p0p[4], ah[2], al[2]);
            split_tf32(p1p[4], ah[3], al[3]);
            const float* bk = vbuf + grp*64 + ((((kk ^ (grp & 3)) << 2) | tig) << 2);
            #pragma unroll
            for (int n = 0; n < 8; n++) {
                float4 bv = *reinterpret_cast<const float4*>(bk + n*512);
                uint32_t bh0 = __float_as_uint(bv.x), bh1 = __float_as_uint(bv.y);
                uint32_t bl0 = __float_as_uint(bv.z), bl1 = __float_as_uint(bv.w);
                MMA_TF32(oacc[n], ah[0], ah[1], ah[2], ah[3], bh0, bh1);
                MMA_TF32(oacc[n], ah[0], ah[1], ah[2], ah[3], bl0, bl1);
                MMA_TF32(oacc[n], al[0], al[1], al[2], al[3], bh0, bh1);
            }
        }
    }

    #pragma unroll
    for (int n = 0; n < 8; n++) {
        const int dcol = n*8 + 2*tig;
        *reinterpret_cast<float2*>(outbase + (size_t)(mrow0 + grp)*DD + dcol) =
            make_float2(oacc[n][0], oacc[n][1]);
        *reinterpret_cast<float2*>(outbase + (size_t)(mrow0 + grp + 8)*DD + dcol) =
            make_float2(oacc[n][2], oacc[n][3]);
    }
}

extern "C" void kernel_launch(void* const* d_in, const int* in_sizes, int n_in,
                              void* d_out, int out_size) {
    const float* q    = (const float*)d_in[0];
    const float* k    = (const float*)d_in[1];
    const float* v    = (const float*)d_in[2];
    const int*   mask = (const int*)d_in[3];

    float* out = (float*)d_out;
    const size_t n_out  = (size_t)NB*NH*SS*DD;
    const size_t n_attn = (size_t)NB*NH*SS*SS;
    float* prob = out + n_out;
    float* attn = prob + n_attn;

    dim3 pgrid(64, NH, NB);
    pack_k_kernel<<<pgrid, 256>>>(k);
    pack_v_kernel<<<pgrid, 256>>>(v);
    pack_mask_kernel<<<(NB*SS*64*32)/256, 256>>>(mask);

    const int smem1 = K1_FLOATS * (int)sizeof(float);   // 68,608 B
    const int smem2 = K2_FLOATS * (int)sizeof(float);   // 68,608 B
    cudaFuncSetAttribute(sdpa_pass1_kernel,
                         cudaFuncAttributeMaxDynamicSharedMemorySize, smem1);
    cudaFuncSetAttribute(sdpa_pass2_kernel,
                         cudaFuncAttributeMaxDynamicSharedMemorySize, smem2);

    dim3 grid(SS/128, NH, NB);
    sdpa_pass1_kernel<<<grid, 256, smem1>>>(q, attn);
    sdpa_pass2_kernel<<<grid, 256, smem2>>>(out, prob, attn);
}

// round 8
// speedup vs baseline: 2.0236x; 1.2641x over previous
#include <cuda_runtime.h>
#include <cstdint>

#define SS 2048
#define DD 64
#define NH 16
#define NB 2
#define NEGV -1000000000.0f
#define LDPS 40

// ---- pass1 smem (floats) ----
#define K1_QPK 0                   // packed Q: 128 rows x 64 = 8192 floats (32KB)
#define K1_DB  8192                // K db: 2 x 2048 floats (8KB tiles)
#define K1_MB  12288               // mask db: 2 x 128 words
#define K1_FLOATS 12544            // 50,176 B

// ---- pass2 smem (floats) ----
#define K2_PS 0                    // raw Ps [128][LDPS]
#define K2_DB (128*LDPS)           // V db: 2 x 2048 floats
#define K2_M  (K2_DB + 4096)
#define K2_LI (K2_M + 128)
#define K2_FLOATS (K2_LI + 128)    // 9,472 floats = 37,888 B

// packed scratch: 64 tiles of 2048 floats per bh
__device__ float    g_kpk[(size_t)NB*NH*64*2048];
__device__ float    g_vpk[(size_t)NB*NH*64*2048];
__device__ unsigned g_mbits[(size_t)NB*SS*64];
__device__ float    g_ml[(size_t)NB*NH*SS*2];

#define MMA_BF16(d, a0,a1,a2,a3, b0,b1) \
    asm volatile("mma.sync.aligned.m16n8k16.row.col.f32.bf16.bf16.f32 " \
        "{%0,%1,%2,%3}, {%4,%5,%6,%7}, {%8,%9}, {%0,%1,%2,%3};" \
        : "+f"((d)[0]), "+f"((d)[1]), "+f"((d)[2]), "+f"((d)[3]) \
        : "r"(a0), "r"(a1), "r"(a2), "r"(a3), "r"(b0), "r"(b1))

// pack (x0,x1) -> bf16x2 {lo=x0, hi=x1}
__device__ __forceinline__ uint32_t bf16pair(float x0, float x1) {
    uint32_t r;
    asm("cvt.rn.bf16x2.f32 %0, %1, %2;" : "=r"(r) : "f"(x1), "f"(x0));
    return r;
}
// split pair into bf16 hi-pair and lo-pair (residual)
__device__ __forceinline__ void split_pair(float x0, float x1, uint32_t& hi, uint32_t& lo) {
    hi = bf16pair(x0, x1);
    float h0 = __uint_as_float(hi << 16);
    float h1 = __uint_as_float(hi & 0xffff0000u);
    lo = bf16pair(x0 - h0, x1 - h1);
}
__device__ __forceinline__ uint32_t smem_u32(const void* p) {
    uint32_t a;
    asm("{ .reg .u64 t; cvta.to.shared.u64 t, %1; cvt.u32.u64 %0, t; }" : "=r"(a) : "l"(p));
    return a;
}
// slot layouts (float offsets); slot = 4 floats(=uint4) {bh0,bh1,bl0,bl1}
__device__ __forceinline__ int pk_q(int row, int kk, int tg) {   // 64 floats/row, kk 0..3
    return row*64 + ((((kk ^ (row & 3)) << 2) | tg) << 2);
}
__device__ __forceinline__ int pk_v(int d, int kk, int tg) {     // 32 floats/row, kk 0..1
    return d*32 + ((((kk ^ (d & 1)) << 2) | tg) << 2);
}
__device__ __forceinline__ void cp16(uint32_t dst, const void* src) {
    asm volatile("cp.async.cg.shared.global [%0], [%1], 16;" :: "r"(dst), "l"(src));
}
__device__ __forceinline__ void cp4(uint32_t dst, const void* src) {
    asm volatile("cp.async.ca.shared.global [%0], [%1], 4;" :: "r"(dst), "l"(src));
}
__device__ __forceinline__ void cp_commit() { asm volatile("cp.async.commit_group;"); }
__device__ __forceinline__ void cp_wait1()  { asm volatile("cp.async.wait_group 1;" ::: "memory"); }
__device__ __forceinline__ void cp_wait0()  { asm volatile("cp.async.wait_group 0;" ::: "memory"); }

// copy one 8KB packed tile (512 float4)
__device__ __forceinline__ void cp_tile8(uint32_t dst_byte, const float* src, int tid) {
    cp16(dst_byte + tid*16, src + tid*4);
    cp16(dst_byte + (tid+256)*16, src + (tid+256)*4);
}

// ---------------- prologue kernels ----------------
__global__ void pack_k_kernel(const float* __restrict__ kg) {
    const int kt = blockIdx.x, h = blockIdx.y, b = blockIdx.z;
    const int bh = b*NH + h;
    const float* base = kg + ((size_t)bh*SS + kt*32) * DD;
    float* out = g_kpk + ((size_t)bh*64 + kt) * 2048;
    for (int s = threadIdx.x; s < 512; s += 256) {
        int r = s >> 4, kk = (s >> 2) & 3, tg = s & 3;
        int c0 = kk*16 + tg*2;
        const float* kp = base + (size_t)r*DD;
        uint32_t bh0, bl0, bh1, bl1;
        split_pair(kp[c0],   kp[c0+1], bh0, bl0);
        split_pair(kp[c0+8], kp[c0+9], bh1, bl1);
        uint4 sv = make_uint4(bh0, bh1, bl0, bl1);
        *reinterpret_cast<uint4*>(out + pk_q(r, kk, tg)) = sv;
    }
}

__global__ void pack_v_kernel(const float* __restrict__ vg) {
    __shared__ float Vs[32*65];
    const int kt = blockIdx.x, h = blockIdx.y, b = blockIdx.z;
    const int bh = b*NH + h;
    const float* base = vg + ((size_t)bh*SS + kt*32) * DD;
    float* out = g_vpk + ((size_t)bh*64 + kt) * 2048;
    for (int i = threadIdx.x; i < 32*16; i += 256) {
        int k = i >> 4, d4 = (i & 15) << 2;
        float4 v = *reinterpret_cast<const float4*>(base + (size_t)k*DD + d4);
        Vs[k*65 + d4 + 0] = v.x; Vs[k*65 + d4 + 1] = v.y;
        Vs[k*65 + d4 + 2] = v.z; Vs[k*65 + d4 + 3] = v.w;
    }
    __syncthreads();
    for (int s = threadIdx.x; s < 512; s += 256) {
        int d = s >> 3, kk = (s >> 2) & 1, tg = s & 3;
        int c0 = kk*16 + tg*2;
        uint32_t bh0, bl0, bh1, bl1;
        split_pair(Vs[c0*65 + d],     Vs[(c0+1)*65 + d], bh0, bl0);
        split_pair(Vs[(c0+8)*65 + d], Vs[(c0+9)*65 + d], bh1, bl1);
        uint4 sv = make_uint4(bh0, bh1, bl0, bl1);
        *reinterpret_cast<uint4*>(out + pk_v(d, kk, tg)) = sv;
    }
}

__global__ void pack_mask_kernel(const int* __restrict__ maskg) {
    int gt = blockIdx.x*256 + threadIdx.x;
    int widx = gt >> 5;
    int lane = gt & 31;
    int w = widx & 63;
    int row = (widx >> 6) & (SS - 1);
    int b = widx >> 17;
    int c = w*32 + lane;
    unsigned nz = maskg[((size_t)b*SS + row)*SS + c] != 0;
    unsigned bits = __ballot_sync(0xffffffffu, nz);
    if (lane == 0) g_mbits[widx] = bits;
}

// ---------------- pass 1: scores + attn + (m, 1/l) ----------------
__global__ __launch_bounds__(256, 4)
void sdpa_pass1_kernel(const float* __restrict__ qg, float* __restrict__ attng)
{
    extern __shared__ float sm[];
    float* Qpk = sm + K1_QPK;
    unsigned* maskbuf = reinterpret_cast<unsigned*>(sm + K1_MB);
    const uint32_t db_byte = smem_u32(sm + K1_DB);
    const uint32_t mb_byte = smem_u32(sm + K1_MB);

    const int tid = threadIdx.x;
    const int wid = tid >> 5;
    const int lid = tid & 31;
    const int grp = lid >> 2;
    const int tig = lid & 3;
    const int mrow0 = wid * 16;

    const int q0 = blockIdx.x * 128;
    const int h  = blockIdx.y;
    const int b  = blockIdx.z;
    const int bh = b*NH + h;

    const float* qbase = qg + ((size_t)bh*SS + q0) * DD;
    float* attnbase = attng + ((size_t)bh*SS + q0) * SS;
    const float* kpk = g_kpk + (size_t)bh*64*2048;
    const unsigned* mbits = g_mbits + ((size_t)b*SS + q0)*64;

    // prefetch K tile 0 + mask col 0
    cp_tile8(db_byte, kpk, tid);
    if (tid < 128) cp4(mb_byte + tid*4, mbits + (size_t)tid*64);
    cp_commit();

    // pack Q once: 2048 slots, 8 per thread
    for (int s = tid; s < 2048; s += 256) {
        int row = s >> 4, kk = (s >> 2) & 3, tg = s & 3;
        int c0 = kk*16 + tg*2;
        const float* qp = qbase + (size_t)row*DD;
        uint32_t h0, l0, h1, l1;
        split_pair(qp[c0],   qp[c0+1], h0, l0);
        split_pair(qp[c0+8], qp[c0+9], h1, l1);
        *reinterpret_cast<uint4*>(Qpk + pk_q(row, kk, tg)) = make_uint4(h0, h1, l0, l1);
    }

    const int g3 = grp & 3;
    const float* arow0 = Qpk + (mrow0 + grp)*64 + tig*4;

    float mrun[2] = {-1e30f, -1e30f};
    float lrun[2] = {0.0f, 0.0f};

    for (int t = 0; t < 64; t++) {
        __syncthreads();
        if (t < 63) {
            cp_tile8(db_byte + ((t+1)&1)*8192, kpk + (size_t)(t+1)*2048, tid);
            if (tid < 128)
                cp4(mb_byte + ((t+1)&1)*512 + tid*4, mbits + (size_t)tid*64 + (t+1));
            cp_commit();
            cp_wait1();
        } else {
            cp_wait0();
        }
        __syncthreads();

        const float* kbuf = sm + K1_DB + (t&1)*2048;
        const float* bbase = kbuf + grp*64 + tig*4;

        float acc[4][4];
        #pragma unroll
        for (int n = 0; n < 4; n++) {
            acc[n][0] = 0.f; acc[n][1] = 0.f; acc[n][2] = 0.f; acc[n][3] = 0.f;
        }

        #pragma unroll
        for (int kk = 0; kk < 4; kk++) {
            uint4 qa = *reinterpret_cast<const uint4*>(arow0 + ((kk ^ g3) << 4));
            uint4 qb = *reinterpret_cast<const uint4*>(arow0 + 512 + ((kk ^ g3) << 4));
            const float* bk = bbase + ((kk ^ g3) << 4);
            #pragma unroll
            for (int n = 0; n < 4; n++) {
                uint4 bv = *reinterpret_cast<const uint4*>(bk + n*512);
                MMA_BF16(acc[n], qa.x, qb.x, qa.y, qb.y, bv.x, bv.y);   // hi*hi
                MMA_BF16(acc[n], qa.x, qb.x, qa.y, qb.y, bv.z, bv.w);   // hi*lo
                MMA_BF16(acc[n], qa.z, qb.z, qa.w, qb.w, bv.x, bv.y);   // lo*hi
            }
        }

        // epilogue: mask bits + scale + attn STG + online (m,l)
        const int r0 = mrow0 + grp, r1 = r0 + 8;
        const unsigned word0 = maskbuf[(t&1)*128 + r0];
        const unsigned word1 = maskbuf[(t&1)*128 + r1];
        float tmax[2] = {-1e30f, -1e30f};
        #pragma unroll
        for (int n = 0; n < 4; n++) {
            const int c = n*8 + 2*tig;
            float s0 = fmaf(acc[n][0], 0.125f, ((word0 >> c) & 1u) ? 0.0f : NEGV);
            float s1 = fmaf(acc[n][1], 0.125f, ((word0 >> (c+1)) & 1u) ? 0.0f : NEGV);
            float s2 = fmaf(acc[n][2], 0.125f, ((word1 >> c) & 1u) ? 0.0f : NEGV);
            float s3 = fmaf(acc[n][3], 0.125f, ((word1 >> (c+1)) & 1u) ? 0.0f : NEGV);
            const int kcol = t*32 + c;
            *reinterpret_cast<float2*>(attnbase + (size_t)r0*SS + kcol) = make_float2(s0, s1);
            *reinterpret_cast<float2*>(attnbase + (size_t)r1*SS + kcol) = make_float2(s2, s3);
            acc[n][0] = s0; acc[n][1] = s1; acc[n][2] = s2; acc[n][3] = s3;
            tmax[0] = fmaxf(tmax[0], fmaxf(s0, s1));
            tmax[1] = fmaxf(tmax[1], fmaxf(s2, s3));
        }
        #pragma unroll
        for (int hh = 0; hh < 2; hh++) {
            float tm = tmax[hh];
            tm = fmaxf(tm, __shfl_xor_sync(0xffffffffu, tm, 1));
            tm = fmaxf(tm, __shfl_xor_sync(0xffffffffu, tm, 2));
            float newm = fmaxf(mrun[hh], tm);
            lrun[hh] *= __expf(mrun[hh] - newm);
            float ls = 0.0f;
            #pragma unroll
            for (int n = 0; n < 4; n++) {
                ls += __expf(acc[n][2*hh+0] - newm);
                ls += __expf(acc[n][2*hh+1] - newm);
            }
            ls += __shfl_xor_sync(0xffffffffu, ls, 1);
            ls += __shfl_xor_sync(0xffffffffu, ls, 2);
            lrun[hh] += ls;
            mrun[hh] = newm;
        }
    }

    if (tig == 0) {
        float* mlb = g_ml + ((size_t)bh*SS + q0)*2;
        mlb[(mrow0 + grp)*2 + 0]     = mrun[0];
        mlb[(mrow0 + grp)*2 + 1]     = 1.0f / lrun[0];
        mlb[(mrow0 + grp + 8)*2 + 0] = mrun[1];
        mlb[(mrow0 + grp + 8)*2 + 1] = 1.0f / lrun[1];
    }
}

// ---------------- pass 2: prob + O ----------------
__global__ __launch_bounds__(256, 3)
void sdpa_pass2_kernel(float* __restrict__ outg, float* __restrict__ probg,
                       const float* __restrict__ attng)
{
    extern __shared__ float sm[];
    float* Ps = sm + K2_PS;
    float* sm_m  = sm + K2_M;
    float* sm_li = sm + K2_LI;
    const uint32_t db_byte = smem_u32(sm + K2_DB);

    const int tid = threadIdx.x;
    const int wid = tid >> 5;
    const int lid = tid & 31;
    const int grp = lid >> 2;
    const int tig = lid & 3;
    const int mrow0 = wid * 16;

    const int q0 = blockIdx.x * 128;
    const int h  = blockIdx.y;
    const int b  = blockIdx.z;
    const int bh = b*NH + h;

    const float* attnbase = attng + ((size_t)bh*SS + q0) * SS;
    float* probbase = probg + ((size_t)bh*SS + q0) * SS;
    float* outbase  = outg  + ((size_t)bh*SS + q0) * DD;
    const float* vpk = g_vpk + (size_t)bh*64*2048;

    if (tid < 128) {
        const float* mlb = g_ml + ((size_t)bh*SS + q0)*2;
        sm_m [tid] = mlb[tid*2 + 0];
        sm_li[tid] = mlb[tid*2 + 1];
    }

    cp_tile8(db_byte, vpk, tid);
    cp_commit();
    __syncthreads();   // m/li visible

    float oacc[8][4];
    #pragma unroll
    for (int n = 0; n < 8; n++) {
        oacc[n][0] = 0.f; oacc[n][1] = 0.f; oacc[n][2] = 0.f; oacc[n][3] = 0.f;
    }

    const int g1 = grp & 1;

    for (int t = 0; t < 64; t++) {
        __syncthreads();
        if (t < 63) {
            cp_tile8(db_byte + ((t+1)&1)*8192, vpk + (size_t)(t+1)*2048, tid);
            cp_commit();
            cp_wait1();
        } else {
            cp_wait0();
        }
        __syncthreads();

        // warp-private staging of Ps rows mrow0..+15 (32 cols)
        #pragma unroll
        for (int j = 0; j < 4; j++) {
            int idx = j*32 + lid;
            int row = mrow0 + (idx >> 3);
            int c4  = (idx & 7) << 2;
            size_t gi = (size_t)row*SS + t*32 + c4;
            float4 sv = *reinterpret_cast<const float4*>(attnbase + gi);
            float mm = sm_m[row], li = sm_li[row];
            float4 pv;
            pv.x = __expf(sv.x - mm) * li;
            pv.y = __expf(sv.y - mm) * li;
            pv.z = __expf(sv.z - mm) * li;
            pv.w = __expf(sv.w - mm) * li;
            *reinterpret_cast<float4*>(probbase + gi) = pv;
            *reinterpret_cast<float4*>(&Ps[row*LDPS + c4]) = pv;
        }
        __syncwarp();

        const float* vbuf = sm + K2_DB + (t&1)*2048;
        #pragma unroll
        for (int kk = 0; kk < 2; kk++) {
            const float* r0p = &Ps[(mrow0 + grp)*LDPS + kk*16 + 2*tig];
            const float* r1p = r0p + 8*LDPS;
            float2 a01 = *reinterpret_cast<const float2*>(r0p);
            float2 a23 = *reinterpret_cast<const float2*>(r0p + 8);
            float2 b01 = *reinterpret_cast<const float2*>(r1p);
            float2 b23 = *reinterpret_cast<const float2*>(r1p + 8);
            uint32_t ah0, al0, ah1, al1, ah2, al2, ah3, al3;
            split_pair(a01.x, a01.y, ah0, al0);
            split_pair(b01.x, b01.y, ah1, al1);
            split_pair(a23.x, a23.y, ah2, al2);
            split_pair(b23.x, b23.y, ah3, al3);
            const float* vb = vbuf + grp*32 + tig*4 + ((kk ^ g1) << 4);
            #pragma unroll
            for (int n = 0; n < 8; n++) {
                uint4 bv = *reinterpret_cast<const uint4*>(vb + n*256);
                MMA_BF16(oacc[n], ah0, ah1, ah2, ah3, bv.x, bv.y);
                MMA_BF16(oacc[n], ah0, ah1, ah2, ah3, bv.z, bv.w);
                MMA_BF16(oacc[n], al0, al1, al2, al3, bv.x, bv.y);
            }
        }
    }

    #pragma unroll
    for (int n = 0; n < 8; n++) {
        const int dcol = n*8 + 2*tig;
        *reinterpret_cast<float2*>(outbase + (size_t)(mrow0 + grp)*DD + dcol) =
            make_float2(oacc[n][0], oacc[n][1]);
        *reinterpret_cast<float2*>(outbase + (size_t)(mrow0 + grp + 8)*DD + dcol) =
            make_float2(oacc[n][2], oacc[n][3]);
    }
}

extern "C" void kernel_launch(void* const* d_in, const int* in_sizes, int n_in,
                              void* d_out, int out_size) {
    const float* q    = (const float*)d_in[0];
    const float* k    = (const float*)d_in[1];
    const float* v    = (const float*)d_in[2];
    const int*   mask = (const int*)d_in[3];

    float* out = (float*)d_out;
    const size_t n_out  = (size_t)NB*NH*SS*DD;
    const size_t n_attn = (size_t)NB*NH*SS*SS;
    float* prob = out + n_out;
    float* attn = prob + n_attn;

    dim3 pgrid(64, NH, NB);
    pack_k_kernel<<<pgrid, 256>>>(k);
    pack_v_kernel<<<pgrid, 256>>>(v);
    pack_mask_kernel<<<(NB*SS*64*32)/256, 256>>>(mask);

    const int smem1 = K1_FLOATS * (int)sizeof(float);   // 50,176 B
    const int smem2 = K2_FLOATS * (int)sizeof(float);   // 37,888 B
    cudaFuncSetAttribute(sdpa_pass1_kernel,
                         cudaFuncAttributeMaxDynamicSharedMemorySize, smem1);
    cudaFuncSetAttribute(sdpa_pass2_kernel,
                         cudaFuncAttributeMaxDynamicSharedMemorySize, smem2);

    dim3 grid(SS/128, NH, NB);
    sdpa_pass1_kernel<<<grid, 256, smem1>>>(q, attn);
    sdpa_pass2_kernel<<<grid, 256, smem2>>>(out, prob, attn);
}

// round 9
// speedup vs baseline: 2.2545x; 1.1141x over previous
#include <cuda_runtime.h>
#include <cstdint>

#define SS 2048
#define DD 64
#define NH 16
#define NB 2
#define NEGV -1000000000.0f
#define LDPS 40

// ---- pass1 smem (floats) ----
#define K1_QPK 0                   // packed Q: 128 rows x 64 = 8192 floats (32KB)
#define K1_DB  8192                // K db: 2 x 2048 floats (8KB tiles)
#define K1_MB  12288               // mask db: 2 x 128 words
#define K1_FLOATS 12544            // 50,176 B

// ---- pass2 smem (floats) ----
#define K2_PS 0                    // raw Ps [128][LDPS]
#define K2_DB (128*LDPS)           // V db: 2 x 2048 floats
#define K2_M  (K2_DB + 4096)
#define K2_LI (K2_M + 128)
#define K2_FLOATS (K2_LI + 128)    // 9,472 floats = 37,888 B

// packed scratch: 64 tiles of 2048 floats per bh
__device__ float    g_kpk[(size_t)NB*NH*64*2048];
__device__ float    g_vpk[(size_t)NB*NH*64*2048];
__device__ unsigned g_mbits[(size_t)NB*SS*64];
__device__ float    g_ml[(size_t)NB*NH*SS*2];

#define MMA_BF16(d, a0,a1,a2,a3, b0,b1) \
    asm volatile("mma.sync.aligned.m16n8k16.row.col.f32.bf16.bf16.f32 " \
        "{%0,%1,%2,%3}, {%4,%5,%6,%7}, {%8,%9}, {%0,%1,%2,%3};" \
        : "+f"((d)[0]), "+f"((d)[1]), "+f"((d)[2]), "+f"((d)[3]) \
        : "r"(a0), "r"(a1), "r"(a2), "r"(a3), "r"(b0), "r"(b1))

__device__ __forceinline__ uint32_t bf16pair(float x0, float x1) {
    uint32_t r;
    asm("cvt.rn.bf16x2.f32 %0, %1, %2;" : "=r"(r) : "f"(x1), "f"(x0));
    return r;
}
__device__ __forceinline__ void split_pair(float x0, float x1, uint32_t& hi, uint32_t& lo) {
    hi = bf16pair(x0, x1);
    float h0 = __uint_as_float(hi << 16);
    float h1 = __uint_as_float(hi & 0xffff0000u);
    lo = bf16pair(x0 - h0, x1 - h1);
}
__device__ __forceinline__ uint32_t smem_u32(const void* p) {
    uint32_t a;
    asm("{ .reg .u64 t; cvta.to.shared.u64 t, %1; cvt.u32.u64 %0, t; }" : "=r"(a) : "l"(p));
    return a;
}
__device__ __forceinline__ int pk_q(int row, int kk, int tg) {   // 64 floats/row, kk 0..3
    return row*64 + ((((kk ^ (row & 3)) << 2) | tg) << 2);
}
__device__ __forceinline__ int pk_v(int d, int kk, int tg) {     // 32 floats/row, kk 0..1
    return d*32 + ((((kk ^ (d & 1)) << 2) | tg) << 2);
}
__device__ __forceinline__ void cp16(uint32_t dst, const void* src) {
    asm volatile("cp.async.cg.shared.global [%0], [%1], 16;" :: "r"(dst), "l"(src));
}
__device__ __forceinline__ void cp4(uint32_t dst, const void* src) {
    asm volatile("cp.async.ca.shared.global [%0], [%1], 4;" :: "r"(dst), "l"(src));
}
__device__ __forceinline__ void cp_commit() { asm volatile("cp.async.commit_group;"); }
__device__ __forceinline__ void cp_wait0()  { asm volatile("cp.async.wait_group 0;" ::: "memory"); }

__device__ __forceinline__ void cp_tile8(uint32_t dst_byte, const float* src, int tid) {
    cp16(dst_byte + tid*16, src + tid*4);
    cp16(dst_byte + (tid+256)*16, src + (tid+256)*4);
}

// ---------------- prologue kernels ----------------
__global__ void pack_k_kernel(const float* __restrict__ kg) {
    const int kt = blockIdx.x, h = blockIdx.y, b = blockIdx.z;
    const int bh = b*NH + h;
    const float* base = kg + ((size_t)bh*SS + kt*32) * DD;
    float* out = g_kpk + ((size_t)bh*64 + kt) * 2048;
    for (int s = threadIdx.x; s < 512; s += 256) {
        int r = s >> 4, kk = (s >> 2) & 3, tg = s & 3;
        int c0 = kk*16 + tg*2;
        const float* kp = base + (size_t)r*DD;
        uint32_t bh0, bl0, bh1, bl1;
        split_pair(kp[c0],   kp[c0+1], bh0, bl0);
        split_pair(kp[c0+8], kp[c0+9], bh1, bl1);
        *reinterpret_cast<uint4*>(out + pk_q(r, kk, tg)) = make_uint4(bh0, bh1, bl0, bl1);
    }
}

__global__ void pack_v_kernel(const float* __restrict__ vg) {
    __shared__ float Vs[32*65];
    const int kt = blockIdx.x, h = blockIdx.y, b = blockIdx.z;
    const int bh = b*NH + h;
    const float* base = vg + ((size_t)bh*SS + kt*32) * DD;
    float* out = g_vpk + ((size_t)bh*64 + kt) * 2048;
    for (int i = threadIdx.x; i < 32*16; i += 256) {
        int k = i >> 4, d4 = (i & 15) << 2;
        float4 v = *reinterpret_cast<const float4*>(base + (size_t)k*DD + d4);
        Vs[k*65 + d4 + 0] = v.x; Vs[k*65 + d4 + 1] = v.y;
        Vs[k*65 + d4 + 2] = v.z; Vs[k*65 + d4 + 3] = v.w;
    }
    __syncthreads();
    for (int s = threadIdx.x; s < 512; s += 256) {
        int d = s >> 3, kk = (s >> 2) & 1, tg = s & 3;
        int c0 = kk*16 + tg*2;
        uint32_t bh0, bl0, bh1, bl1;
        split_pair(Vs[c0*65 + d],     Vs[(c0+1)*65 + d], bh0, bl0);
        split_pair(Vs[(c0+8)*65 + d], Vs[(c0+9)*65 + d], bh1, bl1);
        *reinterpret_cast<uint4*>(out + pk_v(d, kk, tg)) = make_uint4(bh0, bh1, bl0, bl1);
    }
}

__global__ void pack_mask_kernel(const int* __restrict__ maskg) {
    int gt = blockIdx.x*256 + threadIdx.x;
    int widx = gt >> 5;
    int lane = gt & 31;
    int w = widx & 63;
    int row = (widx >> 6) & (SS - 1);
    int b = widx >> 17;
    int c = w*32 + lane;
    unsigned nz = maskg[((size_t)b*SS + row)*SS + c] != 0;
    unsigned bits = __ballot_sync(0xffffffffu, nz);
    if (lane == 0) g_mbits[widx] = bits;
}

// ---------------- pass 1: scores + attn + (m, 1/l) ----------------
__global__ __launch_bounds__(256, 4)
void sdpa_pass1_kernel(const float* __restrict__ qg, float* __restrict__ attng)
{
    extern __shared__ float sm[];
    float* Qpk = sm + K1_QPK;
    unsigned* maskbuf = reinterpret_cast<unsigned*>(sm + K1_MB);
    const uint32_t db_byte = smem_u32(sm + K1_DB);
    const uint32_t mb_byte = smem_u32(sm + K1_MB);

    const int tid = threadIdx.x;
    const int wid = tid >> 5;
    const int lid = tid & 31;
    const int grp = lid >> 2;
    const int tig = lid & 3;
    const int mrow0 = wid * 16;

    const int q0 = blockIdx.x * 128;
    const int h  = blockIdx.y;
    const int b  = blockIdx.z;
    const int bh = b*NH + h;

    const float* qbase = qg + ((size_t)bh*SS + q0) * DD;
    float* attnbase = attng + ((size_t)bh*SS + q0) * SS;
    const float* kpk = g_kpk + (size_t)bh*64*2048;
    const unsigned* mbits = g_mbits + ((size_t)b*SS + q0)*64;

    // prefetch K tile 0 + mask col 0
    cp_tile8(db_byte, kpk, tid);
    if (tid < 128) cp4(mb_byte + tid*4, mbits + (size_t)tid*64);
    cp_commit();

    // pack Q once
    for (int s = tid; s < 2048; s += 256) {
        int row = s >> 4, kk = (s >> 2) & 3, tg = s & 3;
        int c0 = kk*16 + tg*2;
        const float* qp = qbase + (size_t)row*DD;
        uint32_t h0, l0, h1, l1;
        split_pair(qp[c0],   qp[c0+1], h0, l0);
        split_pair(qp[c0+8], qp[c0+9], h1, l1);
        *reinterpret_cast<uint4*>(Qpk + pk_q(row, kk, tg)) = make_uint4(h0, h1, l0, l1);
    }

    const int g3 = grp & 3;
    const float* arow0 = Qpk + (mrow0 + grp)*64 + tig*4;

    float mrun[2] = {-1e30f, -1e30f};
    float lrun[2] = {0.0f, 0.0f};

    for (int t = 0; t < 64; t++) {
        cp_wait0();        // my copies of tile t (and mask t) landed
        __syncthreads();   // everyone's copies visible; compute(t-1) fully done
        if (t < 63) {      // issue t+1 into buf freed by compute(t-1)
            cp_tile8(db_byte + ((t+1)&1)*8192, kpk + (size_t)(t+1)*2048, tid);
            if (tid < 128)
                cp4(mb_byte + ((t+1)&1)*512 + tid*4, mbits + (size_t)tid*64 + (t+1));
            cp_commit();
        }

        const float* kbuf = sm + K1_DB + (t&1)*2048;
        const float* bbase = kbuf + grp*64 + tig*4;

        float acc[4][4];
        #pragma unroll
        for (int n = 0; n < 4; n++) {
            acc[n][0] = 0.f; acc[n][1] = 0.f; acc[n][2] = 0.f; acc[n][3] = 0.f;
        }

        #pragma unroll
        for (int kk = 0; kk < 4; kk++) {
            uint4 qa = *reinterpret_cast<const uint4*>(arow0 + ((kk ^ g3) << 4));
            uint4 qb = *reinterpret_cast<const uint4*>(arow0 + 512 + ((kk ^ g3) << 4));
            const float* bk = bbase + ((kk ^ g3) << 4);
            #pragma unroll
            for (int n = 0; n < 4; n++) {
                uint4 bv = *reinterpret_cast<const uint4*>(bk + n*512);
                MMA_BF16(acc[n], qa.x, qb.x, qa.y, qb.y, bv.x, bv.y);   // hi*hi
                MMA_BF16(acc[n], qa.x, qb.x, qa.y, qb.y, bv.z, bv.w);   // hi*lo
                MMA_BF16(acc[n], qa.z, qb.z, qa.w, qb.w, bv.x, bv.y);   // lo*hi
            }
        }

        // epilogue
        const int r0 = mrow0 + grp, r1 = r0 + 8;
        const unsigned word0 = maskbuf[(t&1)*128 + r0];
        const unsigned word1 = maskbuf[(t&1)*128 + r1];
        float tmax[2] = {-1e30f, -1e30f};
        #pragma unroll
        for (int n = 0; n < 4; n++) {
            const int c = n*8 + 2*tig;
            float s0 = fmaf(acc[n][0], 0.125f, ((word0 >> c) & 1u) ? 0.0f : NEGV);
            float s1 = fmaf(acc[n][1], 0.125f, ((word0 >> (c+1)) & 1u) ? 0.0f : NEGV);
            float s2 = fmaf(acc[n][2], 0.125f, ((word1 >> c) & 1u) ? 0.0f : NEGV);
            float s3 = fmaf(acc[n][3], 0.125f, ((word1 >> (c+1)) & 1u) ? 0.0f : NEGV);
            const int kcol = t*32 + c;
            *reinterpret_cast<float2*>(attnbase + (size_t)r0*SS + kcol) = make_float2(s0, s1);
            *reinterpret_cast<float2*>(attnbase + (size_t)r1*SS + kcol) = make_float2(s2, s3);
            acc[n][0] = s0; acc[n][1] = s1; acc[n][2] = s2; acc[n][3] = s3;
            tmax[0] = fmaxf(tmax[0], fmaxf(s0, s1));
            tmax[1] = fmaxf(tmax[1], fmaxf(s2, s3));
        }
        #pragma unroll
        for (int hh = 0; hh < 2; hh++) {
            float tm = tmax[hh];
            tm = fmaxf(tm, __shfl_xor_sync(0xffffffffu, tm, 1));
            tm = fmaxf(tm, __shfl_xor_sync(0xffffffffu, tm, 2));
            float newm = fmaxf(mrun[hh], tm);
            lrun[hh] *= __expf(mrun[hh] - newm);
            float ls = 0.0f;
            #pragma unroll
            for (int n = 0; n < 4; n++) {
                ls += __expf(acc[n][2*hh+0] - newm);
                ls += __expf(acc[n][2*hh+1] - newm);
            }
            ls += __shfl_xor_sync(0xffffffffu, ls, 1);
            ls += __shfl_xor_sync(0xffffffffu, ls, 2);
            lrun[hh] += ls;
            mrun[hh] = newm;
        }
    }

    if (tig == 0) {
        float* mlb = g_ml + ((size_t)bh*SS + q0)*2;
        mlb[(mrow0 + grp)*2 + 0]     = mrun[0];
        mlb[(mrow0 + grp)*2 + 1]     = 1.0f / lrun[0];
        mlb[(mrow0 + grp + 8)*2 + 0] = mrun[1];
        mlb[(mrow0 + grp + 8)*2 + 1] = 1.0f / lrun[1];
    }
}

// ---------------- pass 2: prob + O ----------------
__global__ __launch_bounds__(256, 4)
void sdpa_pass2_kernel(float* __restrict__ outg, float* __restrict__ probg,
                       const float* __restrict__ attng)
{
    extern __shared__ float sm[];
    float* Ps = sm + K2_PS;
    float* sm_m  = sm + K2_M;
    float* sm_li = sm + K2_LI;
    const uint32_t db_byte = smem_u32(sm + K2_DB);

    const int tid = threadIdx.x;
    const int wid = tid >> 5;
    const int lid = tid & 31;
    const int grp = lid >> 2;
    const int tig = lid & 3;
    const int mrow0 = wid * 16;

    const int q0 = blockIdx.x * 128;
    const int h  = blockIdx.y;
    const int b  = blockIdx.z;
    const int bh = b*NH + h;

    const float* attnbase = attng + ((size_t)bh*SS + q0) * SS;
    float* probbase = probg + ((size_t)bh*SS + q0) * SS;
    float* outbase  = outg  + ((size_t)bh*SS + q0) * DD;
    const float* vpk = g_vpk + (size_t)bh*64*2048;

    if (tid < 128) {
        const float* mlb = g_ml + ((size_t)bh*SS + q0)*2;
        sm_m [tid] = mlb[tid*2 + 0];
        sm_li[tid] = mlb[tid*2 + 1];
    }

    cp_tile8(db_byte, vpk, tid);
    cp_commit();

    float oacc[8][4];
    #pragma unroll
    for (int n = 0; n < 8; n++) {
        oacc[n][0] = 0.f; oacc[n][1] = 0.f; oacc[n][2] = 0.f; oacc[n][3] = 0.f;
    }

    const int g1 = grp & 1;

    for (int t = 0; t < 64; t++) {
        cp_wait0();
        __syncthreads();   // V buf t visible; compute(t-1) done; m/li visible (t=0)
        if (t < 63) {
            cp_tile8(db_byte + ((t+1)&1)*8192, vpk + (size_t)(t+1)*2048, tid);
            cp_commit();
        }

        // warp-private staging of Ps rows mrow0..+15 (overlaps cp of t+1)
        #pragma unroll
        for (int j = 0; j < 4; j++) {
            int idx = j*32 + lid;
            int row = mrow0 + (idx >> 3);
            int c4  = (idx & 7) << 2;
            size_t gi = (size_t)row*SS + t*32 + c4;
            float4 sv = *reinterpret_cast<const float4*>(attnbase + gi);
            float mm = sm_m[row], li = sm_li[row];
            float4 pv;
            pv.x = __expf(sv.x - mm) * li;
            pv.y = __expf(sv.y - mm) * li;
            pv.z = __expf(sv.z - mm) * li;
            pv.w = __expf(sv.w - mm) * li;
            *reinterpret_cast<float4*>(probbase + gi) = pv;
            *reinterpret_cast<float4*>(&Ps[row*LDPS + c4]) = pv;
        }
        __syncwarp();

        const float* vbuf = sm + K2_DB + (t&1)*2048;
        #pragma unroll
        for (int kk = 0; kk < 2; kk++) {
            const float* r0p = &Ps[(mrow0 + grp)*LDPS + kk*16 + 2*tig];
            const float* r1p = r0p + 8*LDPS;
            float2 a01 = *reinterpret_cast<const float2*>(r0p);
            float2 a23 = *reinterpret_cast<const float2*>(r0p + 8);
            float2 b01 = *reinterpret_cast<const float2*>(r1p);
            float2 b23 = *reinterpret_cast<const float2*>(r1p + 8);
            uint32_t ah0, al0, ah1, al1, ah2, al2, ah3, al3;
            split_pair(a01.x, a01.y, ah0, al0);
            split_pair(b01.x, b01.y, ah1, al1);
            split_pair(a23.x, a23.y, ah2, al2);
            split_pair(b23.x, b23.y, ah3, al3);
            const float* vb = vbuf + grp*32 + tig*4 + ((kk ^ g1) << 4);
            #pragma unroll
            for (int n = 0; n < 8; n++) {
                uint4 bv = *reinterpret_cast<const uint4*>(vb + n*256);
                MMA_BF16(oacc[n], ah0, ah1, ah2, ah3, bv.x, bv.y);
                MMA_BF16(oacc[n], ah0, ah1, ah2, ah3, bv.z, bv.w);
                MMA_BF16(oacc[n], al0, al1, al2, al3, bv.x, bv.y);
            }
        }
    }

    #pragma unroll
    for (int n = 0; n < 8; n++) {
        const int dcol = n*8 + 2*tig;
        *reinterpret_cast<float2*>(outbase + (size_t)(mrow0 + grp)*DD + dcol) =
            make_float2(oacc[n][0], oacc[n][1]);
        *reinterpret_cast<float2*>(outbase + (size_t)(mrow0 + grp + 8)*DD + dcol) =
            make_float2(oacc[n][2], oacc[n][3]);
    }
}

extern "C" void kernel_launch(void* const* d_in, const int* in_sizes, int n_in,
                              void* d_out, int out_size) {
    const float* q    = (const float*)d_in[0];
    const float* k    = (const float*)d_in[1];
    const float* v    = (const float*)d_in[2];
    const int*   mask = (const int*)d_in[3];

    float* out = (float*)d_out;
    const size_t n_out  = (size_t)NB*NH*SS*DD;
    const size_t n_attn = (size_t)NB*NH*SS*SS;
    float* prob = out + n_out;
    float* attn = prob + n_attn;

    dim3 pgrid(64, NH, NB);
    pack_k_kernel<<<pgrid, 256>>>(k);
    pack_v_kernel<<<pgrid, 256>>>(v);
    pack_mask_kernel<<<(NB*SS*64*32)/256, 256>>>(mask);

    const int smem1 = K1_FLOATS * (int)sizeof(float);   // 50,176 B
    const int smem2 = K2_FLOATS * (int)sizeof(float);   // 37,888 B
    cudaFuncSetAttribute(sdpa_pass1_kernel,
                         cudaFuncAttributeMaxDynamicSharedMemorySize, smem1);
    cudaFuncSetAttribute(sdpa_pass2_kernel,
                         cudaFuncAttributeMaxDynamicSharedMemorySize, smem2);

    dim3 grid(SS/128, NH, NB);
    sdpa_pass1_kernel<<<grid, 256, smem1>>>(q, attn);
    sdpa_pass2_kernel<<<grid, 256, smem2>>>(out, prob, attn);
}

// round 10
// speedup vs baseline: 2.3137x; 1.0263x over previous
#include <cuda_runtime.h>
#include <cstdint>

#define SS 2048
#define DD 64
#define NH 16
#define NB 2
#define NEGV -1000000000.0f

// ---- pass1 smem (floats) ----
#define K1_QPK 0                   // packed Q: 128 x 64 = 8192 floats (32KB)
#define K1_DB  8192                // K db: 2 x 2048 floats (8KB tiles)
#define K1_MB  12288               // mask db: 2 x 128 words
#define K1_FLOATS 12544            // 50,176 B

// ---- pass2 smem (floats) ----
#define K2_PS 0                    // packed Ps: 128 x 32 = 4096 floats
#define K2_DB 4096                 // V db: 2 x 2048 floats
#define K2_M  (K2_DB + 4096)
#define K2_LI (K2_M + 128)
#define K2_FLOATS (K2_LI + 128)    // 8448 floats = 33,792 B

// packed scratch: 64 tiles of 2048 floats per bh
__device__ float    g_kpk[(size_t)NB*NH*64*2048];
__device__ float    g_vpk[(size_t)NB*NH*64*2048];
__device__ unsigned g_mbits[(size_t)NB*SS*64];
__device__ float    g_ml[(size_t)NB*NH*SS*2];

#define MMA_BF16(d, a0,a1,a2,a3, b0,b1) \
    asm volatile("mma.sync.aligned.m16n8k16.row.col.f32.bf16.bf16.f32 " \
        "{%0,%1,%2,%3}, {%4,%5,%6,%7}, {%8,%9}, {%0,%1,%2,%3};" \
        : "+f"((d)[0]), "+f"((d)[1]), "+f"((d)[2]), "+f"((d)[3]) \
        : "r"(a0), "r"(a1), "r"(a2), "r"(a3), "r"(b0), "r"(b1))

__device__ __forceinline__ uint32_t bf16pair(float x0, float x1) {
    uint32_t r;
    asm("cvt.rn.bf16x2.f32 %0, %1, %2;" : "=r"(r) : "f"(x1), "f"(x0));
    return r;
}
__device__ __forceinline__ void split_pair(float x0, float x1, uint32_t& hi, uint32_t& lo) {
    hi = bf16pair(x0, x1);
    float h0 = __uint_as_float(hi << 16);
    float h1 = __uint_as_float(hi & 0xffff0000u);
    lo = bf16pair(x0 - h0, x1 - h1);
}
__device__ __forceinline__ uint32_t smem_u32(const void* p) {
    uint32_t a;
    asm("{ .reg .u64 t; cvta.to.shared.u64 t, %1; cvt.u32.u64 %0, t; }" : "=r"(a) : "l"(p));
    return a;
}
// pass1 slot (order {h0,h1,l0,l1}): 64 floats/row, kk 0..3
__device__ __forceinline__ int pk_q(int row, int kk, int tg) {
    return row*64 + ((((kk ^ (row & 3)) << 2) | tg) << 2);
}
// V slot (order {h0,h1,l0,l1}): 32 floats/row, kk 0..1
__device__ __forceinline__ int pk_v(int d, int kk, int tg) {
    return d*32 + ((((kk ^ (d & 1)) << 2) | tg) << 2);
}
// P slot (order {h0,l0,h1,l1}): 32 floats/row, kk 0..1
__device__ __forceinline__ int pk_p(int row, int kk, int tg) {
    return row*32 + ((((kk ^ (row & 1)) << 2) | tg) << 2);
}
__device__ __forceinline__ void cp16(uint32_t dst, const void* src) {
    asm volatile("cp.async.cg.shared.global [%0], [%1], 16;" :: "r"(dst), "l"(src));
}
__device__ __forceinline__ void cp4(uint32_t dst, const void* src) {
    asm volatile("cp.async.ca.shared.global [%0], [%1], 4;" :: "r"(dst), "l"(src));
}
__device__ __forceinline__ void cp_commit() { asm volatile("cp.async.commit_group;"); }
__device__ __forceinline__ void cp_wait0()  { asm volatile("cp.async.wait_group 0;" ::: "memory"); }

__device__ __forceinline__ void cp_tile8(uint32_t dst_byte, const float* src, int tid) {
    cp16(dst_byte + tid*16, src + tid*4);
    cp16(dst_byte + (tid+256)*16, src + (tid+256)*4);
}

// ---------------- prologue kernels ----------------
__global__ void pack_k_kernel(const float* __restrict__ kg) {
    const int kt = blockIdx.x, h = blockIdx.y, b = blockIdx.z;
    const int bh = b*NH + h;
    const float* base = kg + ((size_t)bh*SS + kt*32) * DD;
    float* out = g_kpk + ((size_t)bh*64 + kt) * 2048;
    for (int s = threadIdx.x; s < 512; s += 256) {
        int r = s >> 4, kk = (s >> 2) & 3, tg = s & 3;
        int c0 = kk*16 + tg*2;
        const float* kp = base + (size_t)r*DD;
        uint32_t bh0, bl0, bh1, bl1;
        split_pair(kp[c0],   kp[c0+1], bh0, bl0);
        split_pair(kp[c0+8], kp[c0+9], bh1, bl1);
        *reinterpret_cast<uint4*>(out + pk_q(r, kk, tg)) = make_uint4(bh0, bh1, bl0, bl1);
    }
}

__global__ void pack_v_kernel(const float* __restrict__ vg) {
    __shared__ float Vs[32*65];
    const int kt = blockIdx.x, h = blockIdx.y, b = blockIdx.z;
    const int bh = b*NH + h;
    const float* base = vg + ((size_t)bh*SS + kt*32) * DD;
    float* out = g_vpk + ((size_t)bh*64 + kt) * 2048;
    for (int i = threadIdx.x; i < 32*16; i += 256) {
        int k = i >> 4, d4 = (i & 15) << 2;
        float4 v = *reinterpret_cast<const float4*>(base + (size_t)k*DD + d4);
        Vs[k*65 + d4 + 0] = v.x; Vs[k*65 + d4 + 1] = v.y;
        Vs[k*65 + d4 + 2] = v.z; Vs[k*65 + d4 + 3] = v.w;
    }
    __syncthreads();
    for (int s = threadIdx.x; s < 512; s += 256) {
        int d = s >> 3, kk = (s >> 2) & 1, tg = s & 3;
        int c0 = kk*16 + tg*2;
        uint32_t bh0, bl0, bh1, bl1;
        split_pair(Vs[c0*65 + d],     Vs[(c0+1)*65 + d], bh0, bl0);
        split_pair(Vs[(c0+8)*65 + d], Vs[(c0+9)*65 + d], bh1, bl1);
        *reinterpret_cast<uint4*>(out + pk_v(d, kk, tg)) = make_uint4(bh0, bh1, bl0, bl1);
    }
}

__global__ void pack_mask_kernel(const int* __restrict__ maskg) {
    int gt = blockIdx.x*256 + threadIdx.x;
    int widx = gt >> 5;
    int lane = gt & 31;
    int w = widx & 63;
    int row = (widx >> 6) & (SS - 1);
    int b = widx >> 17;
    int c = w*32 + lane;
    unsigned nz = maskg[((size_t)b*SS + row)*SS + c] != 0;
    unsigned bits = __ballot_sync(0xffffffffu, nz);
    if (lane == 0) g_mbits[widx] = bits;
}

// ---------------- pass 1: scores + attn + (m, 1/l) ----------------
__global__ __launch_bounds__(256, 4)
void sdpa_pass1_kernel(const float* __restrict__ qg, float* __restrict__ attng)
{
    extern __shared__ float sm[];
    float* Qpk = sm + K1_QPK;
    unsigned* maskbuf = reinterpret_cast<unsigned*>(sm + K1_MB);
    const uint32_t db_byte = smem_u32(sm + K1_DB);
    const uint32_t mb_byte = smem_u32(sm + K1_MB);

    const int tid = threadIdx.x;
    const int wid = tid >> 5;
    const int lid = tid & 31;
    const int grp = lid >> 2;
    const int tig = lid & 3;
    const int mrow0 = wid * 16;

    const int q0 = blockIdx.x * 128;
    const int h  = blockIdx.y;
    const int b  = blockIdx.z;
    const int bh = b*NH + h;

    const float* qbase = qg + ((size_t)bh*SS + q0) * DD;
    float* attnbase = attng + ((size_t)bh*SS + q0) * SS;
    const float* kpk = g_kpk + (size_t)bh*64*2048;
    const unsigned* mbits = g_mbits + ((size_t)b*SS + q0)*64;

    // prefetch K tile 0 + mask col 0
    cp_tile8(db_byte, kpk, tid);
    if (tid < 128) cp4(mb_byte + tid*4, mbits + (size_t)tid*64);
    cp_commit();

    // pack Q once, pre-scaled by 0.125 (exact power-of-two; numerics unchanged)
    for (int s = tid; s < 2048; s += 256) {
        int row = s >> 4, kk = (s >> 2) & 3, tg = s & 3;
        int c0 = kk*16 + tg*2;
        const float* qp = qbase + (size_t)row*DD;
        uint32_t h0, l0, h1, l1;
        split_pair(qp[c0]*0.125f,   qp[c0+1]*0.125f, h0, l0);
        split_pair(qp[c0+8]*0.125f, qp[c0+9]*0.125f, h1, l1);
        *reinterpret_cast<uint4*>(Qpk + pk_q(row, kk, tg)) = make_uint4(h0, h1, l0, l1);
    }

    const int g3 = grp & 3;
    const float* arow0 = Qpk + (mrow0 + grp)*64 + tig*4;

    float mrun[2] = {-1e30f, -1e30f};
    float lrun[2] = {0.0f, 0.0f};

    for (int t = 0; t < 64; t++) {
        cp_wait0();
        __syncthreads();
        if (t < 63) {
            cp_tile8(db_byte + ((t+1)&1)*8192, kpk + (size_t)(t+1)*2048, tid);
            if (tid < 128)
                cp4(mb_byte + ((t+1)&1)*512 + tid*4, mbits + (size_t)tid*64 + (t+1));
            cp_commit();
        }

        const float* kbuf = sm + K1_DB + (t&1)*2048;
        const float* bbase = kbuf + grp*64 + tig*4;

        float acc[4][4];
        #pragma unroll
        for (int n = 0; n < 4; n++) {
            acc[n][0] = 0.f; acc[n][1] = 0.f; acc[n][2] = 0.f; acc[n][3] = 0.f;
        }

        #pragma unroll
        for (int kk = 0; kk < 4; kk++) {
            uint4 qa = *reinterpret_cast<const uint4*>(arow0 + ((kk ^ g3) << 4));
            uint4 qb = *reinterpret_cast<const uint4*>(arow0 + 512 + ((kk ^ g3) << 4));
            const float* bk = bbase + ((kk ^ g3) << 4);
            #pragma unroll
            for (int n = 0; n < 4; n++) {
                uint4 bv = *reinterpret_cast<const uint4*>(bk + n*512);
                MMA_BF16(acc[n], qa.x, qb.x, qa.y, qb.y, bv.x, bv.y);   // hi*hi
                MMA_BF16(acc[n], qa.x, qb.x, qa.y, qb.y, bv.z, bv.w);   // hi*lo
                MMA_BF16(acc[n], qa.z, qb.z, qa.w, qb.w, bv.x, bv.y);   // lo*hi
            }
        }

        // epilogue: mask + attn STG + per-thread online (m,l) — no shuffles
        const int r0 = mrow0 + grp, r1 = r0 + 8;
        const unsigned word0 = maskbuf[(t&1)*128 + r0];
        const unsigned word1 = maskbuf[(t&1)*128 + r1];
        float tmax[2] = {-1e30f, -1e30f};
        #pragma unroll
        for (int n = 0; n < 4; n++) {
            const int c = n*8 + 2*tig;
            float s0 = acc[n][0] + (((word0 >> c) & 1u) ? 0.0f : NEGV);
            float s1 = acc[n][1] + (((word0 >> (c+1)) & 1u) ? 0.0f : NEGV);
            float s2 = acc[n][2] + (((word1 >> c) & 1u) ? 0.0f : NEGV);
            float s3 = acc[n][3] + (((word1 >> (c+1)) & 1u) ? 0.0f : NEGV);
            const int kcol = t*32 + c;
            *reinterpret_cast<float2*>(attnbase + (size_t)r0*SS + kcol) = make_float2(s0, s1);
            *reinterpret_cast<float2*>(attnbase + (size_t)r1*SS + kcol) = make_float2(s2, s3);
            acc[n][0] = s0; acc[n][1] = s1; acc[n][2] = s2; acc[n][3] = s3;
            tmax[0] = fmaxf(tmax[0], fmaxf(s0, s1));
            tmax[1] = fmaxf(tmax[1], fmaxf(s2, s3));
        }
        #pragma unroll
        for (int hh = 0; hh < 2; hh++) {
            float newm = fmaxf(mrun[hh], tmax[hh]);
            lrun[hh] *= __expf(mrun[hh] - newm);
            float ls = 0.0f;
            #pragma unroll
            for (int n = 0; n < 4; n++) {
                ls += __expf(acc[n][2*hh+0] - newm);
                ls += __expf(acc[n][2*hh+1] - newm);
            }
            lrun[hh] += ls;
            mrun[hh] = newm;
        }
    }

    // final cross-lane (tig) combine, once
    #pragma unroll
    for (int hh = 0; hh < 2; hh++) {
        float m = mrun[hh], l = lrun[hh];
        #pragma unroll
        for (int off = 1; off < 4; off <<= 1) {
            float m2 = __shfl_xor_sync(0xffffffffu, m, off);
            float l2 = __shfl_xor_sync(0xffffffffu, l, off);
            float mn = fmaxf(m, m2);
            l = l*__expf(m - mn) + l2*__expf(m2 - mn);
            m = mn;
        }
        mrun[hh] = m; lrun[hh] = l;
    }
    if (tig == 0) {
        float* mlb = g_ml + ((size_t)bh*SS + q0)*2;
        mlb[(mrow0 + grp)*2 + 0]     = mrun[0];
        mlb[(mrow0 + grp)*2 + 1]     = 1.0f / lrun[0];
        mlb[(mrow0 + grp + 8)*2 + 0] = mrun[1];
        mlb[(mrow0 + grp + 8)*2 + 1] = 1.0f / lrun[1];
    }
}

// ---------------- pass 2: prob + O ----------------
__global__ __launch_bounds__(256, 4)
void sdpa_pass2_kernel(float* __restrict__ outg, float* __restrict__ probg,
                       const float* __restrict__ attng)
{
    extern __shared__ float sm[];
    float* Ps = sm + K2_PS;   // packed P
    float* sm_m  = sm + K2_M;
    float* sm_li = sm + K2_LI;
    const uint32_t db_byte = smem_u32(sm + K2_DB);

    const int tid = threadIdx.x;
    const int wid = tid >> 5;
    const int lid = tid & 31;
    const int grp = lid >> 2;
    const int tig = lid & 3;
    const int mrow0 = wid * 16;

    const int q0 = blockIdx.x * 128;
    const int h  = blockIdx.y;
    const int b  = blockIdx.z;
    const int bh = b*NH + h;

    const float* attnbase = attng + ((size_t)bh*SS + q0) * SS;
    float* probbase = probg + ((size_t)bh*SS + q0) * SS;
    float* outbase  = outg  + ((size_t)bh*SS + q0) * DD;
    const float* vpk = g_vpk + (size_t)bh*64*2048;

    if (tid < 128) {
        const float* mlb = g_ml + ((size_t)bh*SS + q0)*2;
        sm_m [tid] = mlb[tid*2 + 0];
        sm_li[tid] = mlb[tid*2 + 1];
    }

    cp_tile8(db_byte, vpk, tid);
    cp_commit();

    float oacc[8][4];
    #pragma unroll
    for (int n = 0; n < 8; n++) {
        oacc[n][0] = 0.f; oacc[n][1] = 0.f; oacc[n][2] = 0.f; oacc[n][3] = 0.f;
    }

    const int prow_base = (mrow0 + grp)*32;
    const int prow_sw   = ((mrow0 + grp) & 1);

    for (int t = 0; t < 64; t++) {
        cp_wait0();
        __syncthreads();   // V buf t visible; compute(t-1) done; m/li visible (t=0)
        if (t < 63) {
            cp_tile8(db_byte + ((t+1)&1)*8192, vpk + (size_t)(t+1)*2048, tid);
            cp_commit();
        }

        // warp-private staging: prob STG + packed-P STS (splits here, off the MMA chain)
        #pragma unroll
        for (int j = 0; j < 4; j++) {
            int idx = j*32 + lid;
            int row = mrow0 + (idx >> 3);
            int c4  = (idx & 7) << 2;
            size_t gi = (size_t)row*SS + t*32 + c4;
            float4 sv = *reinterpret_cast<const float4*>(attnbase + gi);
            float mm = sm_m[row], li = sm_li[row];
            float4 pv;
            pv.x = __expf(sv.x - mm) * li;
            pv.y = __expf(sv.y - mm) * li;
            pv.z = __expf(sv.z - mm) * li;
            pv.w = __expf(sv.w - mm) * li;
            *reinterpret_cast<float4*>(probbase + gi) = pv;
            uint32_t h0, l0, h1, l1;
            split_pair(pv.x, pv.y, h0, l0);
            split_pair(pv.z, pv.w, h1, l1);
            int kk = c4 >> 4;
            int r  = c4 & 15;
            int half = r >> 3;           // 0 or 1
            int tg = (r & 7) >> 1;       // 0 or 2
            uint32_t* sp = reinterpret_cast<uint32_t*>(Ps + pk_p(row, kk, tg) + half*2);
            *reinterpret_cast<uint2*>(sp)     = make_uint2(h0, l0);
            *reinterpret_cast<uint2*>(sp + 4) = make_uint2(h1, l1);   // tg+1 slot
        }
        __syncwarp();

        const float* vbuf = sm + K2_DB + (t&1)*2048;
        #pragma unroll
        for (int kk = 0; kk < 2; kk++) {
            uint4 pa = *reinterpret_cast<const uint4*>(
                Ps + prow_base + ((((kk ^ prow_sw) << 2) | tig) << 2));
            uint4 pb = *reinterpret_cast<const uint4*>(
                Ps + prow_base + 256 + ((((kk ^ prow_sw) << 2) | tig) << 2));
            const float* vb = vbuf + grp*32 + tig*4 + (((kk ^ (grp & 1)) << 4));
            #pragma unroll
            for (int n = 0; n < 8; n++) {
                uint4 bv = *reinterpret_cast<const uint4*>(vb + n*256);
                MMA_BF16(oacc[n], pa.x, pb.x, pa.z, pb.z, bv.x, bv.y);   // hi*hi
                MMA_BF16(oacc[n], pa.x, pb.x, pa.z, pb.z, bv.z, bv.w);   // hi*lo
                MMA_BF16(oacc[n], pa.y, pb.y, pa.w, pb.w, bv.x, bv.y);   // lo*hi
            }
        }
    }

    #pragma unroll
    for (int n = 0; n < 8; n++) {
        const int dcol = n*8 + 2*tig;
        *reinterpret_cast<float2*>(outbase + (size_t)(mrow0 + grp)*DD + dcol) =
            make_float2(oacc[n][0], oacc[n][1]);
        *reinterpret_cast<float2*>(outbase + (size_t)(mrow0 + grp + 8)*DD + dcol) =
            make_float2(oacc[n][2], oacc[n][3]);
    }
}

extern "C" void kernel_launch(void* const* d_in, const int* in_sizes, int n_in,
                              void* d_out, int out_size) {
    const float* q    = (const float*)d_in[0];
    const float* k    = (const float*)d_in[1];
    const float* v    = (const float*)d_in[2];
    const int*   mask = (const int*)d_in[3];

    float* out = (float*)d_out;
    const size_t n_out  = (size_t)NB*NH*SS*DD;
    const size_t n_attn = (size_t)NB*NH*SS*SS;
    float* prob = out + n_out;
    float* attn = prob + n_attn;

    dim3 pgrid(64, NH, NB);
    pack_k_kernel<<<pgrid, 256>>>(k);
    pack_v_kernel<<<pgrid, 256>>>(v);
    pack_mask_kernel<<<(NB*SS*64*32)/256, 256>>>(mask);

    const int smem1 = K1_FLOATS * (int)sizeof(float);   // 50,176 B
    const int smem2 = K2_FLOATS * (int)sizeof(float);   // 33,792 B
    cudaFuncSetAttribute(sdpa_pass1_kernel,
                         cudaFuncAttributeMaxDynamicSharedMemorySize, smem1);
    cudaFuncSetAttribute(sdpa_pass1_kernel,
                         cudaFuncAttributePreferredSharedMemoryCarveout, 100);
    cudaFuncSetAttribute(sdpa_pass2_kernel,
                         cudaFuncAttributeMaxDynamicSharedMemorySize, smem2);
    cudaFuncSetAttribute(sdpa_pass2_kernel,
                         cudaFuncAttributePreferredSharedMemoryCarveout, 100);

    dim3 grid(SS/128, NH, NB);
    sdpa_pass1_kernel<<<grid, 256, smem1>>>(q, attn);
    sdpa_pass2_kernel<<<grid, 256, smem2>>>(out, prob, attn);
}